// round 13
// baseline (speedup 1.0000x reference)
#include <cuda_runtime.h>
#include <cuda_fp16.h>
#include <math.h>
#include <stdint.h>

// ---------------- problem constants ----------------
#define BATCH 16
#define CCH   512
#define HW    4096
#define DHID  2048
#define NHEAD 8
#define HDIM  64
#define PERB  (CCH*HW)
#define LN_EPS 1e-5f

// ---------------- device scratch (allocation-free) ----------------
__device__ float g_QKV[(size_t)BATCH*3*PERB];   // expQ/expK/V per batch: (b, 1536, HW)
__device__ float g_R  [BATCH*PERB];             // residual R = x + hu(attn)
__device__ float g_KVp[8*128*HDIM*HDIM];        // split-K partials
__device__ float g_ksp[8*128*HDIM];             // split-K row-sum partials of expK
__device__ float g_KV [BATCH*NHEAD*HDIM*HDIM];
__device__ float g_qsum[BATCH*HW];
__device__ float g_bqkv[3*CCH];
__device__ float2 g_part[BATCH*128];
__device__ float2 g_stats[BATCH];
// fp16 activations pixel-major (b, p, c)
__device__ __half g_Th[(size_t)BATCH*HW*CCH];
__device__ __half g_Fh[(size_t)BATCH*HW*DHID];
// fp16 weights (stacked: q,k,v,hu,ff1,ff2)
#define WOFF_HU  786432
#define WOFF_FF1 1048576
#define WOFF_FF2 2097152
#define WTOT     3145728
__device__ __half g_Wh[WTOT];

// ================= PTX helpers =================
__device__ __forceinline__ uint32_t smem_u32(const void* p) {
    uint32_t a;
    asm("{ .reg .u64 t; cvta.to.shared.u64 t, %1; cvt.u32.u64 %0, t; }" : "=r"(a) : "l"(p));
    return a;
}
__device__ __forceinline__ void cp16(uint32_t dst, const void* src) {
    asm volatile("cp.async.cg.shared.global [%0], [%1], 16;" :: "r"(dst), "l"(src));
}
__device__ __forceinline__ void cp_commit() {
    asm volatile("cp.async.commit_group;" ::: "memory");
}
template <int N>
__device__ __forceinline__ void cp_wait() {
    asm volatile("cp.async.wait_group %0;" :: "n"(N) : "memory");
}
__device__ __forceinline__ void ldm_x4(uint32_t* r, uint32_t addr) {
    asm volatile("ldmatrix.sync.aligned.m8n8.x4.shared.b16 {%0,%1,%2,%3}, [%4];"
                 : "=r"(r[0]), "=r"(r[1]), "=r"(r[2]), "=r"(r[3]) : "r"(addr));
}
__device__ __forceinline__ void mma_f16(float* c, const uint32_t* a, const uint32_t* b) {
    asm("mma.sync.aligned.m16n8k16.row.col.f32.f16.f16.f32 "
        "{%0,%1,%2,%3}, {%4,%5,%6,%7}, {%8,%9}, {%0,%1,%2,%3};"
        : "+f"(c[0]), "+f"(c[1]), "+f"(c[2]), "+f"(c[3])
        : "r"(a[0]), "r"(a[1]), "r"(a[2]), "r"(a[3]), "r"(b[0]), "r"(b[1]));
}

// fast exp on FMA pipe
__device__ __forceinline__ float fexp(float x) {
    float t = x * 1.4426950408889634f;
    float n = rintf(t);
    float r = t - n;
    float p = 0.00015403530393381609f;
    p = fmaf(p, r, 0.0013333558146428443f);
    p = fmaf(p, r, 0.009618129107628477f);
    p = fmaf(p, r, 0.05550410866482158f);
    p = fmaf(p, r, 0.2402265069591007f);
    p = fmaf(p, r, 0.6931471805599453f);
    p = fmaf(p, r, 1.0f);
    int e = __float2int_rn(n);
    return p * __int_as_float((e + 127) << 23);
}

// ================= block reductions =================
__device__ __forceinline__ float bred_sum(float v) {
    __shared__ float sb[8];
    int lane = threadIdx.x & 31, w = threadIdx.x >> 5;
    #pragma unroll
    for (int o = 16; o; o >>= 1) v += __shfl_down_sync(0xffffffffu, v, o);
    if (lane == 0) sb[w] = v;
    __syncthreads();
    if (threadIdx.x < 32) {
        float r = (lane < 8) ? sb[lane] : 0.f;
        #pragma unroll
        for (int o = 4; o; o >>= 1) r += __shfl_down_sync(0xffffffffu, r, o);
        if (lane == 0) sb[0] = r;
    }
    __syncthreads();
    float out = sb[0];
    __syncthreads();
    return out;
}

// ================= weight conversion + bias pack (one launch) =================
__global__ __launch_bounds__(256) void wconv_all(const float* __restrict__ qw,
                                                 const float* __restrict__ kw,
                                                 const float* __restrict__ vw,
                                                 const float* __restrict__ huw,
                                                 const float* __restrict__ ff1w,
                                                 const float* __restrict__ ff2w,
                                                 const float* __restrict__ qb,
                                                 const float* __restrict__ kb,
                                                 const float* __restrict__ vb,
                                                 __half* __restrict__ h,
                                                 float* __restrict__ bq) {
    int i = blockIdx.x * 256 + threadIdx.x;
    if (i < WTOT) {
        float v;
        if (i < 786432) {
            int seg = i >> 18, off = i & 262143;
            v = (seg == 0) ? qw[off] : (seg == 1) ? kw[off] : vw[off];
        } else if (i < 1048576) {
            v = huw[i - 786432];
        } else if (i < 2097152) {
            v = ff1w[i - 1048576];
        } else {
            v = ff2w[i - 2097152];
        }
        h[i] = __float2half_rn(v);
    } else {
        int j = i - WTOT;
        if (j < 512) bq[j] = qb[j];
        else if (j < 1024) bq[j] = kb[j - 512];
        else if (j < 1536) bq[j] = vb[j - 1024];
    }
}

// ================= LayerNorm stats =================
__global__ __launch_bounds__(256) void ln_stats(const float* __restrict__ in,
                                                float2* __restrict__ part) {
    int b = blockIdx.y, pb = blockIdx.x;
    const float* p = in + (size_t)b * PERB + (size_t)pb * 16384;
    float s = 0.f, q = 0.f;
    #pragma unroll
    for (int i = 0; i < 16; i++) {
        float4 v = *reinterpret_cast<const float4*>(p + (size_t)(threadIdx.x + i * 256) * 4);
        s += v.x + v.y + v.z + v.w;
        q += v.x * v.x + v.y * v.y + v.z * v.z + v.w * v.w;
    }
    s = bred_sum(s);
    q = bred_sum(q);
    if (threadIdx.x == 0) part[b * 128 + pb] = make_float2(s, q);
}
__global__ __launch_bounds__(128) void ln_finalize(const float2* __restrict__ part,
                                                   float2* __restrict__ stats) {
    __shared__ double ss[128], qq[128];
    const int b = blockIdx.x, t = threadIdx.x;
    float2 p = part[b * 128 + t];
    ss[t] = (double)p.x;
    qq[t] = (double)p.y;
    __syncthreads();
    #pragma unroll
    for (int o = 64; o; o >>= 1) {
        if (t < o) { ss[t] += ss[t + o]; qq[t] += qq[t + o]; }
        __syncthreads();
    }
    if (t == 0) {
        double invN = 1.0 / (double)PERB;
        double mu = ss[0] * invN;
        double var = qq[0] * invN - mu * mu;
        double rstd = 1.0 / sqrt(var + (double)LN_EPS);
        stats[b] = make_float2((float)mu, (float)rstd);
    }
}

// ===== activation convert+transpose: fp32 (b,512,HW) -> LN -> fp16 (b,HW,512) =====
template <int DO_OUT>
__global__ __launch_bounds__(256) void conv_t(const float* __restrict__ in,
                                              const float* __restrict__ lnw,
                                              const float* __restrict__ lnb,
                                              const float2* __restrict__ stats,
                                              __half* __restrict__ oh,
                                              float* __restrict__ out32) {
    __shared__ float T[32][33];
    const int p0 = blockIdx.x * 32, c0 = blockIdx.y * 32, b = blockIdx.z;
    const int t = threadIdx.x;
    {
        int cl = t >> 3, p4 = (t & 7) * 4;
        size_t gidx = ((size_t)b * CCH + c0 + cl) * HW + p0 + p4;
        float4 v = *reinterpret_cast<const float4*>(in + gidx);
        float2 st = stats[b];
        size_t widx = (size_t)(c0 + cl) * HW + p0 + p4;
        float4 wv = *reinterpret_cast<const float4*>(lnw + widx);
        float4 bv = *reinterpret_cast<const float4*>(lnb + widx);
        v.x = (v.x - st.x) * st.y * wv.x + bv.x;
        v.y = (v.y - st.x) * st.y * wv.y + bv.y;
        v.z = (v.z - st.x) * st.y * wv.z + bv.z;
        v.w = (v.w - st.x) * st.y * wv.w + bv.w;
        if (DO_OUT) *reinterpret_cast<float4*>(out32 + gidx) = v;
        T[cl][p4 + 0] = v.x; T[cl][p4 + 1] = v.y; T[cl][p4 + 2] = v.z; T[cl][p4 + 3] = v.w;
    }
    __syncthreads();
    {
        int pl = t >> 3, c4 = (t & 7) * 4;
        unsigned short hb[4];
        #pragma unroll
        for (int j = 0; j < 4; j++) {
            __half hv = __float2half_rn(T[c4 + j][pl]);
            hb[j] = *reinterpret_cast<unsigned short*>(&hv);
        }
        uint2 pk;
        pk.x = (unsigned int)hb[0] | ((unsigned int)hb[1] << 16);
        pk.y = (unsigned int)hb[2] | ((unsigned int)hb[3] << 16);
        size_t o = ((size_t)b * HW + p0 + pl) * CCH + c0 + c4;
        *reinterpret_cast<uint2*>(oh + o) = pk;
    }
}

// ================= HMMA fp16 GEMM (mma.sync, cp.async 5-stage, 2 CTA/SM) =================
// EPI 1: +bias+aux -> fp32, + LN partial sums    EPI 2: gelu(+bias) -> fp16 pixel-major
// EPI 5: exp(+bias) if m0<1024 else +bias (QKV)
// EPI 6: ln2(aux)+bias+acc -> fp32 (fused LayerNorm residual epilogue for ff2)
#define GSTAGE 20480
#define NSTG   5
template <int EPI>
__global__ __launch_bounds__(256, 2)
void hmma_gemm(const __half* __restrict__ wh,
               const __half* __restrict__ ah,
               const float* __restrict__ bias, const float* __restrict__ aux,
               float* __restrict__ Out, __half* __restrict__ OutH,
               float2* __restrict__ part,
               const float* __restrict__ lnw, const float* __restrict__ lnb,
               const float2* __restrict__ stats, int K, int M) {
    extern __shared__ unsigned char smem_raw[];
    const uint32_t sb0 = smem_u32(smem_raw);

    const int tid = threadIdx.x;
    const int lane = tid & 31, wid = tid >> 5;
    const int wm = wid & 3, wn = wid >> 2;
    const int n0 = blockIdx.x * 128, m0 = blockIdx.y * 128, b = blockIdx.z;

    const __half* A0 = wh + (size_t)m0 * K;
    const __half* B0 = ah + ((size_t)b * HW + n0) * K;

    const int r0 = tid >> 2, c0c = tid & 3;
    const int r1 = (tid + 256) >> 2;
    const uint32_t s0 = (uint32_t)(r0 * 80 + c0c * 16);
    const uint32_t s1 = (uint32_t)(r1 * 80 + c0c * 16);
    const size_t g0 = (size_t)r0 * K + c0c * 8;
    const size_t g1 = (size_t)r1 * K + c0c * 8;

    const uint32_t aoff = (uint32_t)((wm * 32 + (lane & 15)) * 80 + (lane >> 4) * 16);
    const uint32_t boff = (uint32_t)(10240 +
        (wn * 64 + (lane & 7) + ((lane >> 4) << 3)) * 80 + ((lane >> 3) & 1) * 16);

    float acc[2][8][4];
    #pragma unroll
    for (int i = 0; i < 2; i++)
        #pragma unroll
        for (int j = 0; j < 8; j++)
            #pragma unroll
            for (int q = 0; q < 4; q++) acc[i][j][q] = 0.f;

    const int NIT = K >> 5;

    #pragma unroll
    for (int s = 0; s < 4; s++) {
        uint32_t sbs = sb0 + s * GSTAGE;
        size_t k0 = (size_t)s * 32;
        cp16(sbs + s0,         A0 + g0 + k0);  cp16(sbs + s1,         A0 + g1 + k0);
        cp16(sbs + 10240 + s0, B0 + g0 + k0);  cp16(sbs + 10240 + s1, B0 + g1 + k0);
        cp_commit();
    }

    int cur = 0, nxt = 4;
    for (int it = 0; it < NIT; it++) {
        cp_wait<3>();
        __syncthreads();

        if (it + 4 < NIT) {
            uint32_t sbs = sb0 + nxt * GSTAGE;
            size_t k0 = (size_t)(it + 4) * 32;
            cp16(sbs + s0,         A0 + g0 + k0);  cp16(sbs + s1,         A0 + g1 + k0);
            cp16(sbs + 10240 + s0, B0 + g0 + k0);  cp16(sbs + 10240 + s1, B0 + g1 + k0);
        }
        cp_commit();

        const uint32_t sbs = sb0 + cur * GSTAGE;
        #pragma unroll
        for (int kk = 0; kk < 2; kk++) {
            const uint32_t kb = kk * 32;
            uint32_t ra[2][4], rb[4][4];
            #pragma unroll
            for (int mi = 0; mi < 2; mi++)
                ldm_x4(ra[mi], sbs + aoff + mi * 1280 + kb);
            #pragma unroll
            for (int ni = 0; ni < 4; ni++)
                ldm_x4(rb[ni], sbs + boff + ni * 1280 + kb);
            #pragma unroll
            for (int mi = 0; mi < 2; mi++)
                #pragma unroll
                for (int ni = 0; ni < 4; ni++)
                    #pragma unroll
                    for (int j = 0; j < 2; j++)
                        mma_f16(acc[mi][ni * 2 + j], ra[mi], &rb[ni][j * 2]);
        }
        cur = (cur == NSTG - 1) ? 0 : cur + 1;
        nxt = (nxt == NSTG - 1) ? 0 : nxt + 1;
    }

    if (EPI == 2) {
        cp_wait<0>();
        __syncthreads();
        unsigned short* T = reinterpret_cast<unsigned short*>(smem_raw);   // [128][144]
        const int lm0 = wm * 32 + (lane >> 2);
        const int ln0 = wn * 64 + (lane & 3) * 2;
        #pragma unroll
        for (int mi = 0; mi < 2; mi++) {
            const int mA = lm0 + mi * 16;
            const float bv0 = __ldg(bias + m0 + mA);
            const float bv1 = __ldg(bias + m0 + mA + 8);
            #pragma unroll
            for (int nf = 0; nf < 8; nf++) {
                const int n = ln0 + nf * 8;
                float v0 = acc[mi][nf][0] + bv0;
                float v1 = acc[mi][nf][1] + bv0;
                float v2 = acc[mi][nf][2] + bv1;
                float v3 = acc[mi][nf][3] + bv1;
                v0 = 0.5f * v0 * (1.0f + erff(v0 * 0.70710678118654752f));
                v1 = 0.5f * v1 * (1.0f + erff(v1 * 0.70710678118654752f));
                v2 = 0.5f * v2 * (1.0f + erff(v2 * 0.70710678118654752f));
                v3 = 0.5f * v3 * (1.0f + erff(v3 * 0.70710678118654752f));
                __half h0 = __float2half_rn(v0), h1 = __float2half_rn(v1);
                __half h2 = __float2half_rn(v2), h3 = __float2half_rn(v3);
                T[n * 144 + mA]           = *reinterpret_cast<unsigned short*>(&h0);
                T[(n + 1) * 144 + mA]     = *reinterpret_cast<unsigned short*>(&h1);
                T[n * 144 + mA + 8]       = *reinterpret_cast<unsigned short*>(&h2);
                T[(n + 1) * 144 + mA + 8] = *reinterpret_cast<unsigned short*>(&h3);
            }
        }
        __syncthreads();
        #pragma unroll
        for (int i = 0; i < 8; i++) {
            int cc = tid + i * 256;
            int row = cc >> 4, cq = cc & 15;
            uint4 v = *reinterpret_cast<const uint4*>(T + row * 144 + cq * 8);
            size_t o = ((size_t)b * HW + n0 + row) * (size_t)M + m0 + cq * 8;
            *reinterpret_cast<uint4*>(OutH + o) = v;
        }
    } else {
        const bool doexp = (EPI == 5) && (m0 < 1024);
        const int mrow = m0 + wm * 32 + (lane >> 2);
        const int ncol = n0 + wn * 64 + (lane & 3) * 2;
        float ls = 0.f, lq = 0.f;
        float2 st;
        if (EPI == 6) st = stats[b];
        #pragma unroll
        for (int mi = 0; mi < 2; mi++) {
            const int mA = mrow + mi * 16;
            const float bv0 = __ldg(bias + mA);
            const float bv1 = __ldg(bias + mA + 8);
            #pragma unroll
            for (int nf = 0; nf < 8; nf++) {
                const int n = ncol + nf * 8;
                size_t iA = ((size_t)b * M + mA) * HW + n;
                size_t iB = iA + (size_t)8 * HW;
                float2 v0 = make_float2(acc[mi][nf][0] + bv0, acc[mi][nf][1] + bv0);
                float2 v1 = make_float2(acc[mi][nf][2] + bv1, acc[mi][nf][3] + bv1);
                if (EPI == 5) {
                    if (doexp) {
                        v0.x = fexp(v0.x); v0.y = fexp(v0.y);
                        v1.x = fexp(v1.x); v1.y = fexp(v1.y);
                    }
                } else if (EPI == 1) {
                    float2 a0 = *reinterpret_cast<const float2*>(aux + iA);
                    float2 a1 = *reinterpret_cast<const float2*>(aux + iB);
                    v0.x += a0.x; v0.y += a0.y; v1.x += a1.x; v1.y += a1.y;
                    ls += v0.x + v0.y + v1.x + v1.y;
                    lq += v0.x * v0.x + v0.y * v0.y + v1.x * v1.x + v1.y * v1.y;
                } else if (EPI == 6) {
                    // fused LN2: out = ln2(R) + acc + bias
                    size_t wA = (size_t)mA * HW + n;
                    size_t wB = wA + (size_t)8 * HW;
                    float2 r0 = *reinterpret_cast<const float2*>(aux + iA);
                    float2 r1 = *reinterpret_cast<const float2*>(aux + iB);
                    float2 w0 = *reinterpret_cast<const float2*>(lnw + wA);
                    float2 w1 = *reinterpret_cast<const float2*>(lnw + wB);
                    float2 l0 = *reinterpret_cast<const float2*>(lnb + wA);
                    float2 l1 = *reinterpret_cast<const float2*>(lnb + wB);
                    v0.x += (r0.x - st.x) * st.y * w0.x + l0.x;
                    v0.y += (r0.y - st.x) * st.y * w0.y + l0.y;
                    v1.x += (r1.x - st.x) * st.y * w1.x + l1.x;
                    v1.y += (r1.y - st.x) * st.y * w1.y + l1.y;
                }
                *reinterpret_cast<float2*>(Out + iA) = v0;
                *reinterpret_cast<float2*>(Out + iB) = v1;
            }
        }
        if (EPI == 1) {
            ls = bred_sum(ls);
            lq = bred_sum(lq);
            if (tid == 0)
                part[b * 128 + blockIdx.y * 32 + blockIdx.x] = make_float2(ls, lq);
        }
    }
}

// ===== qsum: per-pixel sum over 512 channels of expQ =====
__global__ __launch_bounds__(256) void colsum(const float* __restrict__ QKV,
                                              float* __restrict__ qsum) {
    int gid = blockIdx.x * 256 + threadIdx.x;
    int b = gid >> 12, pix = gid & 4095;
    const float* base = QKV + (size_t)b * 3 * PERB + pix;
    float s = 0.f;
    #pragma unroll 8
    for (int c = 0; c < CCH; c++) s += base[(size_t)c * HW];
    qsum[gid] = s;
}

// ================= attention =================
__global__ __launch_bounds__(256) void kv_part(const float* __restrict__ QKV,
                                               float* __restrict__ KVp,
                                               float* __restrict__ ksp) {
    const int cx = blockIdx.x;
    const int bh = blockIdx.y;
    const int b = bh >> 3, h = bh & 7;
    const float* Kb = QKV + (size_t)b * 3 * PERB + PERB     + (size_t)h * HDIM * HW;
    const float* Vb = QKV + (size_t)b * 3 * PERB + 2 * PERB + (size_t)h * HDIM * HW;
    __shared__ float Ks[64][65];
    __shared__ float Vs[64][65];
    const int tid = threadIdx.x;
    const int tx = tid & 15, ty = tid >> 4;
    float acc[4][4] = {};
    float ksloc[4] = {0.f, 0.f, 0.f, 0.f};
    const int pbeg = cx * 512, pend = pbeg + 512;
    for (int p0 = pbeg; p0 < pend; p0 += 64) {
        #pragma unroll
        for (int t = 0; t < 4; t++) {
            int lin = tid + t * 256;
            int r = lin >> 4, c4 = (lin & 15) * 4;
            float4 kv4 = *reinterpret_cast<const float4*>(&Kb[(size_t)r * HW + p0 + c4]);
            float4 vv4 = *reinterpret_cast<const float4*>(&Vb[(size_t)r * HW + p0 + c4]);
            ksloc[t] += kv4.x + kv4.y + kv4.z + kv4.w;
            Ks[r][c4 + 0] = kv4.x; Ks[r][c4 + 1] = kv4.y; Ks[r][c4 + 2] = kv4.z; Ks[r][c4 + 3] = kv4.w;
            Vs[r][c4 + 0] = vv4.x; Vs[r][c4 + 1] = vv4.y; Vs[r][c4 + 2] = vv4.z; Vs[r][c4 + 3] = vv4.w;
        }
        __syncthreads();
        #pragma unroll 8
        for (int p = 0; p < 64; p++) {
            float ra[4], rb[4];
            #pragma unroll
            for (int i = 0; i < 4; i++) ra[i] = Ks[ty * 4 + i][p];
            #pragma unroll
            for (int j = 0; j < 4; j++) rb[j] = Vs[tx * 4 + j][p];
            #pragma unroll
            for (int i = 0; i < 4; i++)
                #pragma unroll
                for (int j = 0; j < 4; j++)
                    acc[i][j] = fmaf(ra[i], rb[j], acc[i][j]);
        }
        __syncthreads();
    }
    #pragma unroll
    for (int t = 0; t < 4; t++) {
        float v = ksloc[t];
        #pragma unroll
        for (int o = 8; o; o >>= 1) v += __shfl_down_sync(0xffffffffu, v, o, 16);
        if ((tid & 15) == 0)
            ksp[((size_t)cx * 128 + bh) * HDIM + (tid >> 4) + 16 * t] = v;
    }
    float* out = KVp + ((size_t)cx * 128 + bh) * (HDIM * HDIM);
    #pragma unroll
    for (int i = 0; i < 4; i++)
        #pragma unroll
        for (int j = 0; j < 4; j++)
            out[(ty * 4 + i) * HDIM + tx * 4 + j] = acc[i][j];
}
__global__ __launch_bounds__(256) void kv_reduce(const float* __restrict__ KVp,
                                                 const float* __restrict__ ksp,
                                                 float* __restrict__ KV) {
    __shared__ float kinv_s[HDIM];
    const int bh = blockIdx.x;
    if (threadIdx.x < HDIM) {
        float s = 0.f;
        #pragma unroll
        for (int cx = 0; cx < 8; cx++)
            s += ksp[((size_t)cx * 128 + bh) * HDIM + threadIdx.x];
        kinv_s[threadIdx.x] = 1.f / s;
    }
    __syncthreads();
    #pragma unroll
    for (int t = 0; t < 16; t++) {
        int e = threadIdx.x + t * 256;
        float s = 0.f;
        #pragma unroll
        for (int cx = 0; cx < 8; cx++)
            s += KVp[((size_t)cx * 128 + bh) * (HDIM * HDIM) + e];
        KV[(size_t)bh * HDIM * HDIM + e] = s * kinv_s[e >> 6];
    }
}
__global__ __launch_bounds__(256) void attn_kernel(const float* __restrict__ KV,
                                                   const float* __restrict__ QKV,
                                                   const float* __restrict__ qsum,
                                                   __half* __restrict__ Th) {
    const int bh = blockIdx.y;
    const int p0 = blockIdx.x * 64;
    const int b = bh >> 3, h = bh & 7;
    const float* Qb  = QKV + (size_t)b * 3 * PERB + (size_t)h * HDIM * HW;
    const float* KVb = KV + (size_t)bh * HDIM * HDIM;
    __shared__ float KVs[64][64];
    __shared__ float Qs[64][68];
    __shared__ unsigned short TT[64][72];
    const int tid = threadIdx.x;
    const int tx = tid & 15, ty = tid >> 4;
    #pragma unroll
    for (int t = 0; t < 4; t++) {
        int lin = tid + t * 256;
        int r = lin >> 4, c4 = (lin & 15) * 4;
        *reinterpret_cast<float4*>(&KVs[r][c4]) =
            *reinterpret_cast<const float4*>(&KVb[(size_t)r * HDIM + c4]);
        float4 q4 = *reinterpret_cast<const float4*>(&Qb[(size_t)r * HW + p0 + c4]);
        *reinterpret_cast<float4*>(&Qs[r][c4]) = q4;
    }
    __syncthreads();
    float acc[4][4] = {};
    #pragma unroll 8
    for (int k = 0; k < 64; k++) {
        float4 q4 = *reinterpret_cast<const float4*>(&Qs[k][tx * 4]);
        float4 a4 = *reinterpret_cast<const float4*>(&KVs[k][ty * 4]);
        float ra[4] = {a4.x, a4.y, a4.z, a4.w};
        float rb[4] = {q4.x, q4.y, q4.z, q4.w};
        #pragma unroll
        for (int i = 0; i < 4; i++)
            #pragma unroll
            for (int j = 0; j < 4; j++)
                acc[i][j] = fmaf(ra[i], rb[j], acc[i][j]);
    }
    const int bq = b * HW + p0 + tx * 4;
    float inv[4];
    #pragma unroll
    for (int j = 0; j < 4; j++) inv[j] = 1.f / qsum[bq + j];
    #pragma unroll
    for (int i = 0; i < 4; i++)
        #pragma unroll
        for (int j = 0; j < 4; j++) {
            __half hv = __float2half_rn(acc[i][j] * inv[j]);
            TT[tx * 4 + j][ty * 4 + i] = *reinterpret_cast<unsigned short*>(&hv);
        }
    __syncthreads();
    #pragma unroll
    for (int t = 0; t < 2; t++) {
        int cc = tid + t * 256;
        int p = cc >> 3, co = (cc & 7) * 8;
        uint4 v = *reinterpret_cast<const uint4*>(&TT[p][co]);
        size_t o = ((size_t)b * HW + p0 + p) * CCH + h * 64 + co;
        *reinterpret_cast<uint4*>(Th + o) = v;
    }
}

// ================= launch =================
extern "C" void kernel_launch(void* const* d_in, const int* in_sizes, int n_in,
                              void* d_out, int out_size) {
    const float* x     = (const float*)d_in[0];
    const float* ln1w  = (const float*)d_in[1];
    const float* ln1b  = (const float*)d_in[2];
    const float* qw    = (const float*)d_in[3];
    const float* qb    = (const float*)d_in[4];
    const float* kw    = (const float*)d_in[5];
    const float* kb    = (const float*)d_in[6];
    const float* vw    = (const float*)d_in[7];
    const float* vb    = (const float*)d_in[8];
    const float* huw   = (const float*)d_in[9];
    const float* hub   = (const float*)d_in[10];
    const float* ln2w  = (const float*)d_in[11];
    const float* ln2b  = (const float*)d_in[12];
    const float* ff1w  = (const float*)d_in[13];
    const float* ff1b  = (const float*)d_in[14];
    const float* ff2w  = (const float*)d_in[15];
    const float* ff2b  = (const float*)d_in[16];
    float* out = (float*)d_out;

    float *QKV, *R, *KVp, *ksp, *KV, *qsum, *bqkv;
    float2 *part, *stats;
    __half *Th, *Fh, *Wh;
    cudaGetSymbolAddress((void**)&QKV, g_QKV);
    cudaGetSymbolAddress((void**)&R, g_R);
    cudaGetSymbolAddress((void**)&KVp, g_KVp);
    cudaGetSymbolAddress((void**)&ksp, g_ksp);
    cudaGetSymbolAddress((void**)&KV, g_KV);
    cudaGetSymbolAddress((void**)&qsum, g_qsum);
    cudaGetSymbolAddress((void**)&bqkv, g_bqkv);
    cudaGetSymbolAddress((void**)&part, g_part);
    cudaGetSymbolAddress((void**)&stats, g_stats);
    cudaGetSymbolAddress((void**)&Th, g_Th);
    cudaGetSymbolAddress((void**)&Fh, g_Fh);
    cudaGetSymbolAddress((void**)&Wh, g_Wh);

    const int SMEM = NSTG * GSTAGE;   // 102400
    cudaFuncSetAttribute(hmma_gemm<1>, cudaFuncAttributeMaxDynamicSharedMemorySize, SMEM);
    cudaFuncSetAttribute(hmma_gemm<2>, cudaFuncAttributeMaxDynamicSharedMemorySize, SMEM);
    cudaFuncSetAttribute(hmma_gemm<5>, cudaFuncAttributeMaxDynamicSharedMemorySize, SMEM);
    cudaFuncSetAttribute(hmma_gemm<6>, cudaFuncAttributeMaxDynamicSharedMemorySize, SMEM);

    const dim3 gT(HW / 32, CCH / 32, BATCH);         // (128, 16, 16)
    const dim3 gQKVg(HW / 128, 1536 / 128, BATCH);   // (32, 12, 16)
    const dim3 gG512(HW / 128, CCH / 128, BATCH);    // (32, 4, 16)
    const dim3 gG2048(HW / 128, DHID / 128, BATCH);  // (32, 16, 16)

    // weights + bias (one launch)
    wconv_all<<<(WTOT + 1536) / 256, 256>>>(qw, kw, vw, huw, ff1w, ff2w, qb, kb, vb, Wh, bqkv);

    // ln1 -> Th
    ln_stats<<<dim3(128, BATCH), 256>>>(x, part);
    ln_finalize<<<BATCH, 128>>>(part, stats);
    conv_t<0><<<gT, 256>>>(x, ln1w, ln1b, stats, Th, nullptr);

    // fused QKV GEMM (fp32 out, exp fused for Q/K rows)
    hmma_gemm<5><<<gQKVg, 256, SMEM>>>(Wh, Th, bqkv, nullptr, QKV, nullptr, nullptr,
                                       nullptr, nullptr, nullptr, CCH, 1536);

    colsum<<<(BATCH * HW) / 256, 256>>>(QKV, qsum);

    kv_part<<<dim3(8, 128), 256>>>(QKV, KVp, ksp);
    kv_reduce<<<128, 256>>>(KVp, ksp, KV);
    attn_kernel<<<dim3(HW / 64, BATCH * NHEAD), 256>>>(KV, QKV, qsum, Th);

    // R = x + hu(attn); LN2 partials fused
    hmma_gemm<1><<<gG512, 256, SMEM>>>(Wh + WOFF_HU, Th, hub, x, R, nullptr, part,
                                       nullptr, nullptr, nullptr, CCH, CCH);
    ln_finalize<<<BATCH, 128>>>(part, stats);

    // ln2 -> Th only (fp32 out now produced by ff2's fused epilogue)
    conv_t<0><<<gT, 256>>>(R, ln2w, ln2b, stats, Th, nullptr);

    // Fh = fp16(gelu(ff1)); out = ln2(R) + ff2(Fh)  [fused epilogue]
    hmma_gemm<2><<<gG2048, 256, SMEM>>>(Wh + WOFF_FF1, Th, ff1b, nullptr, nullptr, Fh, nullptr,
                                        nullptr, nullptr, nullptr, CCH, DHID);
    hmma_gemm<6><<<gG512, 256, SMEM>>>(Wh + WOFF_FF2, Fh, ff2b, R, out, nullptr, nullptr,
                                       ln2w, ln2b, stats, DHID, CCH);
}

// round 14
// speedup vs baseline: 1.0349x; 1.0349x over previous
#include <cuda_runtime.h>
#include <cuda_fp16.h>
#include <math.h>
#include <stdint.h>

// ---------------- problem constants ----------------
#define BATCH 16
#define CCH   512
#define HW    4096
#define DHID  2048
#define NHEAD 8
#define HDIM  64
#define PERB  (CCH*HW)
#define LN_EPS 1e-5f

// ---------------- device scratch (allocation-free) ----------------
__device__ float g_QKV[(size_t)BATCH*3*PERB];   // expQ/expK/V per batch: (b, 1536, HW)
__device__ float g_R  [BATCH*PERB];             // residual R = x + hu(attn)
__device__ float g_KVp[8*128*HDIM*HDIM];        // split-K partials
__device__ float g_ksp[8*128*HDIM];             // split-K row-sum partials of expK
__device__ float g_KV [BATCH*NHEAD*HDIM*HDIM];
__device__ float g_qsum[BATCH*HW];
__device__ float g_bqkv[3*CCH];
__device__ float2 g_part[BATCH*128];
__device__ float2 g_stats[BATCH];
// fp16 activations pixel-major (b, p, c)
__device__ __half g_Th[(size_t)BATCH*HW*CCH];
__device__ __half g_Fh[(size_t)BATCH*HW*DHID];
// fp16 weights (stacked: q,k,v,hu,ff1,ff2)
#define WOFF_HU  786432
#define WOFF_FF1 1048576
#define WOFF_FF2 2097152
#define WTOT     3145728
__device__ __half g_Wh[WTOT];

// ================= PTX helpers =================
__device__ __forceinline__ uint32_t smem_u32(const void* p) {
    uint32_t a;
    asm("{ .reg .u64 t; cvta.to.shared.u64 t, %1; cvt.u32.u64 %0, t; }" : "=r"(a) : "l"(p));
    return a;
}
__device__ __forceinline__ void cp16(uint32_t dst, const void* src) {
    asm volatile("cp.async.cg.shared.global [%0], [%1], 16;" :: "r"(dst), "l"(src));
}
__device__ __forceinline__ void cp_commit() {
    asm volatile("cp.async.commit_group;" ::: "memory");
}
template <int N>
__device__ __forceinline__ void cp_wait() {
    asm volatile("cp.async.wait_group %0;" :: "n"(N) : "memory");
}
__device__ __forceinline__ void ldm_x4(uint32_t* r, uint32_t addr) {
    asm volatile("ldmatrix.sync.aligned.m8n8.x4.shared.b16 {%0,%1,%2,%3}, [%4];"
                 : "=r"(r[0]), "=r"(r[1]), "=r"(r[2]), "=r"(r[3]) : "r"(addr));
}
__device__ __forceinline__ void mma_f16(float* c, const uint32_t* a, const uint32_t* b) {
    asm("mma.sync.aligned.m16n8k16.row.col.f32.f16.f16.f32 "
        "{%0,%1,%2,%3}, {%4,%5,%6,%7}, {%8,%9}, {%0,%1,%2,%3};"
        : "+f"(c[0]), "+f"(c[1]), "+f"(c[2]), "+f"(c[3])
        : "r"(a[0]), "r"(a[1]), "r"(a[2]), "r"(a[3]), "r"(b[0]), "r"(b[1]));
}

// fast exp on FMA pipe
__device__ __forceinline__ float fexp(float x) {
    float t = x * 1.4426950408889634f;
    float n = rintf(t);
    float r = t - n;
    float p = 0.00015403530393381609f;
    p = fmaf(p, r, 0.0013333558146428443f);
    p = fmaf(p, r, 0.009618129107628477f);
    p = fmaf(p, r, 0.05550410866482158f);
    p = fmaf(p, r, 0.2402265069591007f);
    p = fmaf(p, r, 0.6931471805599453f);
    p = fmaf(p, r, 1.0f);
    int e = __float2int_rn(n);
    return p * __int_as_float((e + 127) << 23);
}

// ================= block reductions =================
__device__ __forceinline__ float bred_sum(float v) {
    __shared__ float sb[8];
    int lane = threadIdx.x & 31, w = threadIdx.x >> 5;
    #pragma unroll
    for (int o = 16; o; o >>= 1) v += __shfl_down_sync(0xffffffffu, v, o);
    if (lane == 0) sb[w] = v;
    __syncthreads();
    if (threadIdx.x < 32) {
        float r = (lane < 8) ? sb[lane] : 0.f;
        #pragma unroll
        for (int o = 4; o; o >>= 1) r += __shfl_down_sync(0xffffffffu, r, o);
        if (lane == 0) sb[0] = r;
    }
    __syncthreads();
    float out = sb[0];
    __syncthreads();
    return out;
}

// ================= weight conversion + bias pack (one launch) =================
__global__ __launch_bounds__(256) void wconv_all(const float* __restrict__ qw,
                                                 const float* __restrict__ kw,
                                                 const float* __restrict__ vw,
                                                 const float* __restrict__ huw,
                                                 const float* __restrict__ ff1w,
                                                 const float* __restrict__ ff2w,
                                                 const float* __restrict__ qb,
                                                 const float* __restrict__ kb,
                                                 const float* __restrict__ vb,
                                                 __half* __restrict__ h,
                                                 float* __restrict__ bq) {
    int i = blockIdx.x * 256 + threadIdx.x;
    if (i < WTOT) {
        float v;
        if (i < 786432) {
            int seg = i >> 18, off = i & 262143;
            v = (seg == 0) ? qw[off] : (seg == 1) ? kw[off] : vw[off];
        } else if (i < 1048576) {
            v = huw[i - 786432];
        } else if (i < 2097152) {
            v = ff1w[i - 1048576];
        } else {
            v = ff2w[i - 2097152];
        }
        h[i] = __float2half_rn(v);
    } else {
        int j = i - WTOT;
        if (j < 512) bq[j] = qb[j];
        else if (j < 1024) bq[j] = kb[j - 512];
        else if (j < 1536) bq[j] = vb[j - 1024];
    }
}

// ================= LayerNorm stats =================
__global__ __launch_bounds__(256) void ln_stats(const float* __restrict__ in,
                                                float2* __restrict__ part) {
    int b = blockIdx.y, pb = blockIdx.x;
    const float* p = in + (size_t)b * PERB + (size_t)pb * 16384;
    float s = 0.f, q = 0.f;
    #pragma unroll
    for (int i = 0; i < 16; i++) {
        float4 v = *reinterpret_cast<const float4*>(p + (size_t)(threadIdx.x + i * 256) * 4);
        s += v.x + v.y + v.z + v.w;
        q += v.x * v.x + v.y * v.y + v.z * v.z + v.w * v.w;
    }
    s = bred_sum(s);
    q = bred_sum(q);
    if (threadIdx.x == 0) part[b * 128 + pb] = make_float2(s, q);
}
__global__ __launch_bounds__(128) void ln_finalize(const float2* __restrict__ part,
                                                   float2* __restrict__ stats) {
    __shared__ double ss[128], qq[128];
    const int b = blockIdx.x, t = threadIdx.x;
    float2 p = part[b * 128 + t];
    ss[t] = (double)p.x;
    qq[t] = (double)p.y;
    __syncthreads();
    #pragma unroll
    for (int o = 64; o; o >>= 1) {
        if (t < o) { ss[t] += ss[t + o]; qq[t] += qq[t + o]; }
        __syncthreads();
    }
    if (t == 0) {
        double invN = 1.0 / (double)PERB;
        double mu = ss[0] * invN;
        double var = qq[0] * invN - mu * mu;
        double rstd = 1.0 / sqrt(var + (double)LN_EPS);
        stats[b] = make_float2((float)mu, (float)rstd);
    }
}

// ===== activation convert+transpose: fp32 (b,512,HW) -> LN -> fp16 (b,HW,512) =====
template <int DO_OUT>
__global__ __launch_bounds__(256) void conv_t(const float* __restrict__ in,
                                              const float* __restrict__ lnw,
                                              const float* __restrict__ lnb,
                                              const float2* __restrict__ stats,
                                              __half* __restrict__ oh,
                                              float* __restrict__ out32) {
    __shared__ float T[32][33];
    const int p0 = blockIdx.x * 32, c0 = blockIdx.y * 32, b = blockIdx.z;
    const int t = threadIdx.x;
    {
        int cl = t >> 3, p4 = (t & 7) * 4;
        size_t gidx = ((size_t)b * CCH + c0 + cl) * HW + p0 + p4;
        float4 v = *reinterpret_cast<const float4*>(in + gidx);
        float2 st = stats[b];
        size_t widx = (size_t)(c0 + cl) * HW + p0 + p4;
        float4 wv = *reinterpret_cast<const float4*>(lnw + widx);
        float4 bv = *reinterpret_cast<const float4*>(lnb + widx);
        v.x = (v.x - st.x) * st.y * wv.x + bv.x;
        v.y = (v.y - st.x) * st.y * wv.y + bv.y;
        v.z = (v.z - st.x) * st.y * wv.z + bv.z;
        v.w = (v.w - st.x) * st.y * wv.w + bv.w;
        if (DO_OUT) *reinterpret_cast<float4*>(out32 + gidx) = v;
        T[cl][p4 + 0] = v.x; T[cl][p4 + 1] = v.y; T[cl][p4 + 2] = v.z; T[cl][p4 + 3] = v.w;
    }
    __syncthreads();
    {
        int pl = t >> 3, c4 = (t & 7) * 4;
        unsigned short hb[4];
        #pragma unroll
        for (int j = 0; j < 4; j++) {
            __half hv = __float2half_rn(T[c4 + j][pl]);
            hb[j] = *reinterpret_cast<unsigned short*>(&hv);
        }
        uint2 pk;
        pk.x = (unsigned int)hb[0] | ((unsigned int)hb[1] << 16);
        pk.y = (unsigned int)hb[2] | ((unsigned int)hb[3] << 16);
        size_t o = ((size_t)b * HW + p0 + pl) * CCH + c0 + c4;
        *reinterpret_cast<uint2*>(oh + o) = pk;
    }
}

// ================= HMMA fp16 GEMM (mma.sync, cp.async 4-stage, 2 CTA/SM) =================
// EPI 1: +bias+aux -> fp32, + LN partial sums    EPI 2: gelu(+bias) -> fp16 pixel-major
// EPI 5: exp(+bias) if m0<1024 else +bias (QKV)
// EPI 6: ln2(aux)+bias+acc -> fp32 (fused LayerNorm residual epilogue for ff2)
#define GSTAGE 20480
template <int EPI>
__global__ __launch_bounds__(256, 2)
void hmma_gemm(const __half* __restrict__ wh,
               const __half* __restrict__ ah,
               const float* __restrict__ bias, const float* __restrict__ aux,
               float* __restrict__ Out, __half* __restrict__ OutH,
               float2* __restrict__ part,
               const float* __restrict__ lnw, const float* __restrict__ lnb,
               const float2* __restrict__ stats, int K, int M) {
    extern __shared__ unsigned char smem_raw[];
    const uint32_t sb0 = smem_u32(smem_raw);

    const int tid = threadIdx.x;
    const int lane = tid & 31, wid = tid >> 5;
    const int wm = wid & 3, wn = wid >> 2;
    const int n0 = blockIdx.x * 128, m0 = blockIdx.y * 128, b = blockIdx.z;

    const __half* A0 = wh + (size_t)m0 * K;
    const __half* B0 = ah + ((size_t)b * HW + n0) * K;

    const int r0 = tid >> 2, c0c = tid & 3;
    const int r1 = (tid + 256) >> 2;
    const uint32_t s0 = (uint32_t)(r0 * 80 + c0c * 16);
    const uint32_t s1 = (uint32_t)(r1 * 80 + c0c * 16);
    const size_t g0 = (size_t)r0 * K + c0c * 8;
    const size_t g1 = (size_t)r1 * K + c0c * 8;

    const uint32_t aoff = (uint32_t)((wm * 32 + (lane & 15)) * 80 + (lane >> 4) * 16);
    const uint32_t boff = (uint32_t)(10240 +
        (wn * 64 + (lane & 7) + ((lane >> 4) << 3)) * 80 + ((lane >> 3) & 1) * 16);

    float acc[2][8][4];
    #pragma unroll
    for (int i = 0; i < 2; i++)
        #pragma unroll
        for (int j = 0; j < 8; j++)
            #pragma unroll
            for (int q = 0; q < 4; q++) acc[i][j][q] = 0.f;

    const int NIT = K >> 5;

    #pragma unroll
    for (int s = 0; s < 3; s++) {
        uint32_t sbs = sb0 + s * GSTAGE;
        size_t k0 = (size_t)s * 32;
        cp16(sbs + s0,         A0 + g0 + k0);  cp16(sbs + s1,         A0 + g1 + k0);
        cp16(sbs + 10240 + s0, B0 + g0 + k0);  cp16(sbs + 10240 + s1, B0 + g1 + k0);
        cp_commit();
    }

    for (int it = 0; it < NIT; it++) {
        cp_wait<2>();
        __syncthreads();

        if (it + 3 < NIT) {
            int ls = (it + 3) & 3;
            uint32_t sbs = sb0 + ls * GSTAGE;
            size_t k0 = (size_t)(it + 3) * 32;
            cp16(sbs + s0,         A0 + g0 + k0);  cp16(sbs + s1,         A0 + g1 + k0);
            cp16(sbs + 10240 + s0, B0 + g0 + k0);  cp16(sbs + 10240 + s1, B0 + g1 + k0);
        }
        cp_commit();

        const uint32_t sbs = sb0 + (it & 3) * GSTAGE;
        #pragma unroll
        for (int kk = 0; kk < 2; kk++) {
            const uint32_t kb = kk * 32;
            uint32_t ra[2][4], rb[4][4];
            #pragma unroll
            for (int mi = 0; mi < 2; mi++)
                ldm_x4(ra[mi], sbs + aoff + mi * 1280 + kb);
            #pragma unroll
            for (int ni = 0; ni < 4; ni++)
                ldm_x4(rb[ni], sbs + boff + ni * 1280 + kb);
            #pragma unroll
            for (int mi = 0; mi < 2; mi++)
                #pragma unroll
                for (int ni = 0; ni < 4; ni++)
                    #pragma unroll
                    for (int j = 0; j < 2; j++)
                        mma_f16(acc[mi][ni * 2 + j], ra[mi], &rb[ni][j * 2]);
        }
    }

    if (EPI == 2) {
        cp_wait<0>();
        __syncthreads();
        unsigned short* T = reinterpret_cast<unsigned short*>(smem_raw);   // [128][144]
        const int lm0 = wm * 32 + (lane >> 2);
        const int ln0 = wn * 64 + (lane & 3) * 2;
        #pragma unroll
        for (int mi = 0; mi < 2; mi++) {
            const int mA = lm0 + mi * 16;
            const float bv0 = __ldg(bias + m0 + mA);
            const float bv1 = __ldg(bias + m0 + mA + 8);
            #pragma unroll
            for (int nf = 0; nf < 8; nf++) {
                const int n = ln0 + nf * 8;
                float v0 = acc[mi][nf][0] + bv0;
                float v1 = acc[mi][nf][1] + bv0;
                float v2 = acc[mi][nf][2] + bv1;
                float v3 = acc[mi][nf][3] + bv1;
                v0 = 0.5f * v0 * (1.0f + erff(v0 * 0.70710678118654752f));
                v1 = 0.5f * v1 * (1.0f + erff(v1 * 0.70710678118654752f));
                v2 = 0.5f * v2 * (1.0f + erff(v2 * 0.70710678118654752f));
                v3 = 0.5f * v3 * (1.0f + erff(v3 * 0.70710678118654752f));
                __half h0 = __float2half_rn(v0), h1 = __float2half_rn(v1);
                __half h2 = __float2half_rn(v2), h3 = __float2half_rn(v3);
                T[n * 144 + mA]           = *reinterpret_cast<unsigned short*>(&h0);
                T[(n + 1) * 144 + mA]     = *reinterpret_cast<unsigned short*>(&h1);
                T[n * 144 + mA + 8]       = *reinterpret_cast<unsigned short*>(&h2);
                T[(n + 1) * 144 + mA + 8] = *reinterpret_cast<unsigned short*>(&h3);
            }
        }
        __syncthreads();
        #pragma unroll
        for (int i = 0; i < 8; i++) {
            int cc = tid + i * 256;
            int row = cc >> 4, cq = cc & 15;
            uint4 v = *reinterpret_cast<const uint4*>(T + row * 144 + cq * 8);
            size_t o = ((size_t)b * HW + n0 + row) * (size_t)M + m0 + cq * 8;
            *reinterpret_cast<uint4*>(OutH + o) = v;
        }
    } else {
        const bool doexp = (EPI == 5) && (m0 < 1024);
        const int mrow = m0 + wm * 32 + (lane >> 2);
        const int ncol = n0 + wn * 64 + (lane & 3) * 2;
        float ls = 0.f, lq = 0.f;
        float2 st;
        if (EPI == 6) st = stats[b];
        #pragma unroll
        for (int mi = 0; mi < 2; mi++) {
            const int mA = mrow + mi * 16;
            const float bv0 = __ldg(bias + mA);
            const float bv1 = __ldg(bias + mA + 8);
            #pragma unroll
            for (int nf = 0; nf < 8; nf++) {
                const int n = ncol + nf * 8;
                size_t iA = ((size_t)b * M + mA) * HW + n;
                size_t iB = iA + (size_t)8 * HW;
                float2 v0 = make_float2(acc[mi][nf][0] + bv0, acc[mi][nf][1] + bv0);
                float2 v1 = make_float2(acc[mi][nf][2] + bv1, acc[mi][nf][3] + bv1);
                if (EPI == 5) {
                    if (doexp) {
                        v0.x = fexp(v0.x); v0.y = fexp(v0.y);
                        v1.x = fexp(v1.x); v1.y = fexp(v1.y);
                    }
                } else if (EPI == 1) {
                    float2 a0 = *reinterpret_cast<const float2*>(aux + iA);
                    float2 a1 = *reinterpret_cast<const float2*>(aux + iB);
                    v0.x += a0.x; v0.y += a0.y; v1.x += a1.x; v1.y += a1.y;
                    ls += v0.x + v0.y + v1.x + v1.y;
                    lq += v0.x * v0.x + v0.y * v0.y + v1.x * v1.x + v1.y * v1.y;
                } else if (EPI == 6) {
                    // fused LN2: out = ln2(R) + acc + bias
                    size_t wA = (size_t)mA * HW + n;
                    size_t wB = wA + (size_t)8 * HW;
                    float2 r0 = *reinterpret_cast<const float2*>(aux + iA);
                    float2 r1 = *reinterpret_cast<const float2*>(aux + iB);
                    float2 w0 = *reinterpret_cast<const float2*>(lnw + wA);
                    float2 w1 = *reinterpret_cast<const float2*>(lnw + wB);
                    float2 l0 = *reinterpret_cast<const float2*>(lnb + wA);
                    float2 l1 = *reinterpret_cast<const float2*>(lnb + wB);
                    v0.x += (r0.x - st.x) * st.y * w0.x + l0.x;
                    v0.y += (r0.y - st.x) * st.y * w0.y + l0.y;
                    v1.x += (r1.x - st.x) * st.y * w1.x + l1.x;
                    v1.y += (r1.y - st.x) * st.y * w1.y + l1.y;
                }
                *reinterpret_cast<float2*>(Out + iA) = v0;
                *reinterpret_cast<float2*>(Out + iB) = v1;
            }
        }
        if (EPI == 1) {
            ls = bred_sum(ls);
            lq = bred_sum(lq);
            if (tid == 0)
                part[b * 128 + blockIdx.y * 32 + blockIdx.x] = make_float2(ls, lq);
        }
    }
}

// ===== qsum: per-pixel sum over 512 channels of expQ =====
__global__ __launch_bounds__(256) void colsum(const float* __restrict__ QKV,
                                              float* __restrict__ qsum) {
    int gid = blockIdx.x * 256 + threadIdx.x;
    int b = gid >> 12, pix = gid & 4095;
    const float* base = QKV + (size_t)b * 3 * PERB + pix;
    float s = 0.f;
    #pragma unroll 8
    for (int c = 0; c < CCH; c++) s += base[(size_t)c * HW];
    qsum[gid] = s;
}

// ================= attention =================
__global__ __launch_bounds__(256) void kv_part(const float* __restrict__ QKV,
                                               float* __restrict__ KVp,
                                               float* __restrict__ ksp) {
    const int cx = blockIdx.x;
    const int bh = blockIdx.y;
    const int b = bh >> 3, h = bh & 7;
    const float* Kb = QKV + (size_t)b * 3 * PERB + PERB     + (size_t)h * HDIM * HW;
    const float* Vb = QKV + (size_t)b * 3 * PERB + 2 * PERB + (size_t)h * HDIM * HW;
    __shared__ float Ks[64][65];
    __shared__ float Vs[64][65];
    const int tid = threadIdx.x;
    const int tx = tid & 15, ty = tid >> 4;
    float acc[4][4] = {};
    float ksloc[4] = {0.f, 0.f, 0.f, 0.f};
    const int pbeg = cx * 512, pend = pbeg + 512;
    for (int p0 = pbeg; p0 < pend; p0 += 64) {
        #pragma unroll
        for (int t = 0; t < 4; t++) {
            int lin = tid + t * 256;
            int r = lin >> 4, c4 = (lin & 15) * 4;
            float4 kv4 = *reinterpret_cast<const float4*>(&Kb[(size_t)r * HW + p0 + c4]);
            float4 vv4 = *reinterpret_cast<const float4*>(&Vb[(size_t)r * HW + p0 + c4]);
            ksloc[t] += kv4.x + kv4.y + kv4.z + kv4.w;
            Ks[r][c4 + 0] = kv4.x; Ks[r][c4 + 1] = kv4.y; Ks[r][c4 + 2] = kv4.z; Ks[r][c4 + 3] = kv4.w;
            Vs[r][c4 + 0] = vv4.x; Vs[r][c4 + 1] = vv4.y; Vs[r][c4 + 2] = vv4.z; Vs[r][c4 + 3] = vv4.w;
        }
        __syncthreads();
        #pragma unroll 8
        for (int p = 0; p < 64; p++) {
            float ra[4], rb[4];
            #pragma unroll
            for (int i = 0; i < 4; i++) ra[i] = Ks[ty * 4 + i][p];
            #pragma unroll
            for (int j = 0; j < 4; j++) rb[j] = Vs[tx * 4 + j][p];
            #pragma unroll
            for (int i = 0; i < 4; i++)
                #pragma unroll
                for (int j = 0; j < 4; j++)
                    acc[i][j] = fmaf(ra[i], rb[j], acc[i][j]);
        }
        __syncthreads();
    }
    #pragma unroll
    for (int t = 0; t < 4; t++) {
        float v = ksloc[t];
        #pragma unroll
        for (int o = 8; o; o >>= 1) v += __shfl_down_sync(0xffffffffu, v, o, 16);
        if ((tid & 15) == 0)
            ksp[((size_t)cx * 128 + bh) * HDIM + (tid >> 4) + 16 * t] = v;
    }
    float* out = KVp + ((size_t)cx * 128 + bh) * (HDIM * HDIM);
    #pragma unroll
    for (int i = 0; i < 4; i++)
        #pragma unroll
        for (int j = 0; j < 4; j++)
            out[(ty * 4 + i) * HDIM + tx * 4 + j] = acc[i][j];
}
__global__ __launch_bounds__(256) void kv_reduce(const float* __restrict__ KVp,
                                                 const float* __restrict__ ksp,
                                                 float* __restrict__ KV) {
    __shared__ float kinv_s[HDIM];
    const int bh = blockIdx.x;
    if (threadIdx.x < HDIM) {
        float s = 0.f;
        #pragma unroll
        for (int cx = 0; cx < 8; cx++)
            s += ksp[((size_t)cx * 128 + bh) * HDIM + threadIdx.x];
        kinv_s[threadIdx.x] = 1.f / s;
    }
    __syncthreads();
    #pragma unroll
    for (int t = 0; t < 16; t++) {
        int e = threadIdx.x + t * 256;
        float s = 0.f;
        #pragma unroll
        for (int cx = 0; cx < 8; cx++)
            s += KVp[((size_t)cx * 128 + bh) * (HDIM * HDIM) + e];
        KV[(size_t)bh * HDIM * HDIM + e] = s * kinv_s[e >> 6];
    }
}
__global__ __launch_bounds__(256) void attn_kernel(const float* __restrict__ KV,
                                                   const float* __restrict__ QKV,
                                                   const float* __restrict__ qsum,
                                                   __half* __restrict__ Th) {
    const int bh = blockIdx.y;
    const int p0 = blockIdx.x * 64;
    const int b = bh >> 3, h = bh & 7;
    const float* Qb  = QKV + (size_t)b * 3 * PERB + (size_t)h * HDIM * HW;
    const float* KVb = KV + (size_t)bh * HDIM * HDIM;
    __shared__ float KVs[64][64];
    __shared__ float Qs[64][68];
    __shared__ unsigned short TT[64][72];
    const int tid = threadIdx.x;
    const int tx = tid & 15, ty = tid >> 4;
    #pragma unroll
    for (int t = 0; t < 4; t++) {
        int lin = tid + t * 256;
        int r = lin >> 4, c4 = (lin & 15) * 4;
        *reinterpret_cast<float4*>(&KVs[r][c4]) =
            *reinterpret_cast<const float4*>(&KVb[(size_t)r * HDIM + c4]);
        float4 q4 = *reinterpret_cast<const float4*>(&Qb[(size_t)r * HW + p0 + c4]);
        *reinterpret_cast<float4*>(&Qs[r][c4]) = q4;
    }
    __syncthreads();
    float acc[4][4] = {};
    #pragma unroll 8
    for (int k = 0; k < 64; k++) {
        float4 q4 = *reinterpret_cast<const float4*>(&Qs[k][tx * 4]);
        float4 a4 = *reinterpret_cast<const float4*>(&KVs[k][ty * 4]);
        float ra[4] = {a4.x, a4.y, a4.z, a4.w};
        float rb[4] = {q4.x, q4.y, q4.z, q4.w};
        #pragma unroll
        for (int i = 0; i < 4; i++)
            #pragma unroll
            for (int j = 0; j < 4; j++)
                acc[i][j] = fmaf(ra[i], rb[j], acc[i][j]);
    }
    const int bq = b * HW + p0 + tx * 4;
    float inv[4];
    #pragma unroll
    for (int j = 0; j < 4; j++) inv[j] = 1.f / qsum[bq + j];
    #pragma unroll
    for (int i = 0; i < 4; i++)
        #pragma unroll
        for (int j = 0; j < 4; j++) {
            __half hv = __float2half_rn(acc[i][j] * inv[j]);
            TT[tx * 4 + j][ty * 4 + i] = *reinterpret_cast<unsigned short*>(&hv);
        }
    __syncthreads();
    #pragma unroll
    for (int t = 0; t < 2; t++) {
        int cc = tid + t * 256;
        int p = cc >> 3, co = (cc & 7) * 8;
        uint4 v = *reinterpret_cast<const uint4*>(&TT[p][co]);
        size_t o = ((size_t)b * HW + p0 + p) * CCH + h * 64 + co;
        *reinterpret_cast<uint4*>(Th + o) = v;
    }
}

// ================= launch =================
extern "C" void kernel_launch(void* const* d_in, const int* in_sizes, int n_in,
                              void* d_out, int out_size) {
    const float* x     = (const float*)d_in[0];
    const float* ln1w  = (const float*)d_in[1];
    const float* ln1b  = (const float*)d_in[2];
    const float* qw    = (const float*)d_in[3];
    const float* qb    = (const float*)d_in[4];
    const float* kw    = (const float*)d_in[5];
    const float* kb    = (const float*)d_in[6];
    const float* vw    = (const float*)d_in[7];
    const float* vb    = (const float*)d_in[8];
    const float* huw   = (const float*)d_in[9];
    const float* hub   = (const float*)d_in[10];
    const float* ln2w  = (const float*)d_in[11];
    const float* ln2b  = (const float*)d_in[12];
    const float* ff1w  = (const float*)d_in[13];
    const float* ff1b  = (const float*)d_in[14];
    const float* ff2w  = (const float*)d_in[15];
    const float* ff2b  = (const float*)d_in[16];
    float* out = (float*)d_out;

    float *QKV, *R, *KVp, *ksp, *KV, *qsum, *bqkv;
    float2 *part, *stats;
    __half *Th, *Fh, *Wh;
    cudaGetSymbolAddress((void**)&QKV, g_QKV);
    cudaGetSymbolAddress((void**)&R, g_R);
    cudaGetSymbolAddress((void**)&KVp, g_KVp);
    cudaGetSymbolAddress((void**)&ksp, g_ksp);
    cudaGetSymbolAddress((void**)&KV, g_KV);
    cudaGetSymbolAddress((void**)&qsum, g_qsum);
    cudaGetSymbolAddress((void**)&bqkv, g_bqkv);
    cudaGetSymbolAddress((void**)&part, g_part);
    cudaGetSymbolAddress((void**)&stats, g_stats);
    cudaGetSymbolAddress((void**)&Th, g_Th);
    cudaGetSymbolAddress((void**)&Fh, g_Fh);
    cudaGetSymbolAddress((void**)&Wh, g_Wh);

    const int SMEM = 4 * GSTAGE;   // 81920
    cudaFuncSetAttribute(hmma_gemm<1>, cudaFuncAttributeMaxDynamicSharedMemorySize, SMEM);
    cudaFuncSetAttribute(hmma_gemm<2>, cudaFuncAttributeMaxDynamicSharedMemorySize, SMEM);
    cudaFuncSetAttribute(hmma_gemm<5>, cudaFuncAttributeMaxDynamicSharedMemorySize, SMEM);
    cudaFuncSetAttribute(hmma_gemm<6>, cudaFuncAttributeMaxDynamicSharedMemorySize, SMEM);

    const dim3 gT(HW / 32, CCH / 32, BATCH);         // (128, 16, 16)
    const dim3 gQKVg(HW / 128, 1536 / 128, BATCH);   // (32, 12, 16)
    const dim3 gG512(HW / 128, CCH / 128, BATCH);    // (32, 4, 16)
    const dim3 gG2048(HW / 128, DHID / 128, BATCH);  // (32, 16, 16)

    // weights + bias (one launch)
    wconv_all<<<(WTOT + 1536) / 256, 256>>>(qw, kw, vw, huw, ff1w, ff2w, qb, kb, vb, Wh, bqkv);

    // ln1 -> Th
    ln_stats<<<dim3(128, BATCH), 256>>>(x, part);
    ln_finalize<<<BATCH, 128>>>(part, stats);
    conv_t<0><<<gT, 256>>>(x, ln1w, ln1b, stats, Th, nullptr);

    // fused QKV GEMM (fp32 out, exp fused for Q/K rows)
    hmma_gemm<5><<<gQKVg, 256, SMEM>>>(Wh, Th, bqkv, nullptr, QKV, nullptr, nullptr,
                                       nullptr, nullptr, nullptr, CCH, 1536);

    colsum<<<(BATCH * HW) / 256, 256>>>(QKV, qsum);

    kv_part<<<dim3(8, 128), 256>>>(QKV, KVp, ksp);
    kv_reduce<<<128, 256>>>(KVp, ksp, KV);
    attn_kernel<<<dim3(HW / 64, BATCH * NHEAD), 256>>>(KV, QKV, qsum, Th);

    // R = x + hu(attn); LN2 partials fused
    hmma_gemm<1><<<gG512, 256, SMEM>>>(Wh + WOFF_HU, Th, hub, x, R, nullptr, part,
                                       nullptr, nullptr, nullptr, CCH, CCH);
    ln_finalize<<<BATCH, 128>>>(part, stats);

    // ln2 -> Th only (fp32 out produced by ff2's fused epilogue)
    conv_t<0><<<gT, 256>>>(R, ln2w, ln2b, stats, Th, nullptr);

    // Fh = fp16(gelu(ff1)); out = ln2(R) + ff2(Fh)  [fused epilogue]
    hmma_gemm<2><<<gG2048, 256, SMEM>>>(Wh + WOFF_FF1, Th, ff1b, nullptr, nullptr, Fh, nullptr,
                                        nullptr, nullptr, nullptr, CCH, DHID);
    hmma_gemm<6><<<gG512, 256, SMEM>>>(Wh + WOFF_FF2, Fh, ff2b, R, out, nullptr, nullptr,
                                       ln2w, ln2b, stats, DHID, CCH);
}

// round 15
// speedup vs baseline: 1.0397x; 1.0047x over previous
#include <cuda_runtime.h>
#include <cuda_fp16.h>
#include <math.h>
#include <stdint.h>

// ---------------- problem constants ----------------
#define BATCH 16
#define CCH   512
#define HW    4096
#define DHID  2048
#define NHEAD 8
#define HDIM  64
#define PERB  (CCH*HW)
#define LN_EPS 1e-5f

// ---------------- device scratch (allocation-free) ----------------
__device__ float g_QKV[(size_t)BATCH*3*PERB];   // expQ/expK/V per batch: (b, 1536, HW)
__device__ __half g_Rh[BATCH*PERB];             // residual R = x + hu(attn), fp16
__device__ float g_KVp[8*128*HDIM*HDIM];        // split-K partials
__device__ float g_ksp[8*128*HDIM];             // split-K row-sum partials of expK
__device__ float g_KV [BATCH*NHEAD*HDIM*HDIM];
__device__ float g_qsum[BATCH*HW];
__device__ float g_bqkv[3*CCH];
__device__ float2 g_part[BATCH*128];
__device__ float2 g_stats[BATCH];
// fp16 activations pixel-major (b, p, c)
__device__ __half g_Th[(size_t)BATCH*HW*CCH];
__device__ __half g_Fh[(size_t)BATCH*HW*DHID];
// fp16 weights (stacked: q,k,v,hu,ff1,ff2)
#define WOFF_HU  786432
#define WOFF_FF1 1048576
#define WOFF_FF2 2097152
#define WTOT     3145728
__device__ __half g_Wh[WTOT];

// ================= PTX helpers =================
__device__ __forceinline__ uint32_t smem_u32(const void* p) {
    uint32_t a;
    asm("{ .reg .u64 t; cvta.to.shared.u64 t, %1; cvt.u32.u64 %0, t; }" : "=r"(a) : "l"(p));
    return a;
}
__device__ __forceinline__ void cp16(uint32_t dst, const void* src) {
    asm volatile("cp.async.cg.shared.global [%0], [%1], 16;" :: "r"(dst), "l"(src));
}
__device__ __forceinline__ void cp_commit() {
    asm volatile("cp.async.commit_group;" ::: "memory");
}
template <int N>
__device__ __forceinline__ void cp_wait() {
    asm volatile("cp.async.wait_group %0;" :: "n"(N) : "memory");
}
__device__ __forceinline__ void ldm_x4(uint32_t* r, uint32_t addr) {
    asm volatile("ldmatrix.sync.aligned.m8n8.x4.shared.b16 {%0,%1,%2,%3}, [%4];"
                 : "=r"(r[0]), "=r"(r[1]), "=r"(r[2]), "=r"(r[3]) : "r"(addr));
}
__device__ __forceinline__ void mma_f16(float* c, const uint32_t* a, const uint32_t* b) {
    asm("mma.sync.aligned.m16n8k16.row.col.f32.f16.f16.f32 "
        "{%0,%1,%2,%3}, {%4,%5,%6,%7}, {%8,%9}, {%0,%1,%2,%3};"
        : "+f"(c[0]), "+f"(c[1]), "+f"(c[2]), "+f"(c[3])
        : "r"(a[0]), "r"(a[1]), "r"(a[2]), "r"(a[3]), "r"(b[0]), "r"(b[1]));
}

// fast exp on FMA pipe
__device__ __forceinline__ float fexp(float x) {
    float t = x * 1.4426950408889634f;
    float n = rintf(t);
    float r = t - n;
    float p = 0.00015403530393381609f;
    p = fmaf(p, r, 0.0013333558146428443f);
    p = fmaf(p, r, 0.009618129107628477f);
    p = fmaf(p, r, 0.05550410866482158f);
    p = fmaf(p, r, 0.2402265069591007f);
    p = fmaf(p, r, 0.6931471805599453f);
    p = fmaf(p, r, 1.0f);
    int e = __float2int_rn(n);
    return p * __int_as_float((e + 127) << 23);
}

// ================= block reductions =================
__device__ __forceinline__ float bred_sum(float v) {
    __shared__ float sb[8];
    int lane = threadIdx.x & 31, w = threadIdx.x >> 5;
    #pragma unroll
    for (int o = 16; o; o >>= 1) v += __shfl_down_sync(0xffffffffu, v, o);
    if (lane == 0) sb[w] = v;
    __syncthreads();
    if (threadIdx.x < 32) {
        float r = (lane < 8) ? sb[lane] : 0.f;
        #pragma unroll
        for (int o = 4; o; o >>= 1) r += __shfl_down_sync(0xffffffffu, r, o);
        if (lane == 0) sb[0] = r;
    }
    __syncthreads();
    float out = sb[0];
    __syncthreads();
    return out;
}

// ================= weight conversion + bias pack (one launch) =================
__global__ __launch_bounds__(256) void wconv_all(const float* __restrict__ qw,
                                                 const float* __restrict__ kw,
                                                 const float* __restrict__ vw,
                                                 const float* __restrict__ huw,
                                                 const float* __restrict__ ff1w,
                                                 const float* __restrict__ ff2w,
                                                 const float* __restrict__ qb,
                                                 const float* __restrict__ kb,
                                                 const float* __restrict__ vb,
                                                 __half* __restrict__ h,
                                                 float* __restrict__ bq) {
    int i = blockIdx.x * 256 + threadIdx.x;
    if (i < WTOT) {
        float v;
        if (i < 786432) {
            int seg = i >> 18, off = i & 262143;
            v = (seg == 0) ? qw[off] : (seg == 1) ? kw[off] : vw[off];
        } else if (i < 1048576) {
            v = huw[i - 786432];
        } else if (i < 2097152) {
            v = ff1w[i - 1048576];
        } else {
            v = ff2w[i - 2097152];
        }
        h[i] = __float2half_rn(v);
    } else {
        int j = i - WTOT;
        if (j < 512) bq[j] = qb[j];
        else if (j < 1024) bq[j] = kb[j - 512];
        else if (j < 1536) bq[j] = vb[j - 1024];
    }
}

// ================= LayerNorm stats =================
__global__ __launch_bounds__(256) void ln_stats(const float* __restrict__ in,
                                                float2* __restrict__ part) {
    int b = blockIdx.y, pb = blockIdx.x;
    const float* p = in + (size_t)b * PERB + (size_t)pb * 16384;
    float s = 0.f, q = 0.f;
    #pragma unroll
    for (int i = 0; i < 16; i++) {
        float4 v = *reinterpret_cast<const float4*>(p + (size_t)(threadIdx.x + i * 256) * 4);
        s += v.x + v.y + v.z + v.w;
        q += v.x * v.x + v.y * v.y + v.z * v.z + v.w * v.w;
    }
    s = bred_sum(s);
    q = bred_sum(q);
    if (threadIdx.x == 0) part[b * 128 + pb] = make_float2(s, q);
}
__global__ __launch_bounds__(128) void ln_finalize(const float2* __restrict__ part,
                                                   float2* __restrict__ stats) {
    __shared__ double ss[128], qq[128];
    const int b = blockIdx.x, t = threadIdx.x;
    float2 p = part[b * 128 + t];
    ss[t] = (double)p.x;
    qq[t] = (double)p.y;
    __syncthreads();
    #pragma unroll
    for (int o = 64; o; o >>= 1) {
        if (t < o) { ss[t] += ss[t + o]; qq[t] += qq[t + o]; }
        __syncthreads();
    }
    if (t == 0) {
        double invN = 1.0 / (double)PERB;
        double mu = ss[0] * invN;
        double var = qq[0] * invN - mu * mu;
        double rstd = 1.0 / sqrt(var + (double)LN_EPS);
        stats[b] = make_float2((float)mu, (float)rstd);
    }
}

// ===== conv_t: fp32 (b,512,HW) -> LN -> fp16 (b,HW,512) =====
__global__ __launch_bounds__(256) void conv_t(const float* __restrict__ in,
                                              const float* __restrict__ lnw,
                                              const float* __restrict__ lnb,
                                              const float2* __restrict__ stats,
                                              __half* __restrict__ oh) {
    __shared__ float T[32][33];
    const int p0 = blockIdx.x * 32, c0 = blockIdx.y * 32, b = blockIdx.z;
    const int t = threadIdx.x;
    {
        int cl = t >> 3, p4 = (t & 7) * 4;
        size_t gidx = ((size_t)b * CCH + c0 + cl) * HW + p0 + p4;
        float4 v = *reinterpret_cast<const float4*>(in + gidx);
        float2 st = stats[b];
        size_t widx = (size_t)(c0 + cl) * HW + p0 + p4;
        float4 wv = *reinterpret_cast<const float4*>(lnw + widx);
        float4 bv = *reinterpret_cast<const float4*>(lnb + widx);
        v.x = (v.x - st.x) * st.y * wv.x + bv.x;
        v.y = (v.y - st.x) * st.y * wv.y + bv.y;
        v.z = (v.z - st.x) * st.y * wv.z + bv.z;
        v.w = (v.w - st.x) * st.y * wv.w + bv.w;
        T[cl][p4 + 0] = v.x; T[cl][p4 + 1] = v.y; T[cl][p4 + 2] = v.z; T[cl][p4 + 3] = v.w;
    }
    __syncthreads();
    {
        int pl = t >> 3, c4 = (t & 7) * 4;
        unsigned short hb[4];
        #pragma unroll
        for (int j = 0; j < 4; j++) {
            __half hv = __float2half_rn(T[c4 + j][pl]);
            hb[j] = *reinterpret_cast<unsigned short*>(&hv);
        }
        uint2 pk;
        pk.x = (unsigned int)hb[0] | ((unsigned int)hb[1] << 16);
        pk.y = (unsigned int)hb[2] | ((unsigned int)hb[3] << 16);
        size_t o = ((size_t)b * HW + p0 + pl) * CCH + c0 + c4;
        *reinterpret_cast<uint2*>(oh + o) = pk;
    }
}

// ===== conv_t_h: fp16 R (b,512,HW) -> LN -> fp16 (b,HW,512) =====
__global__ __launch_bounds__(256) void conv_t_h(const __half* __restrict__ in,
                                                const float* __restrict__ lnw,
                                                const float* __restrict__ lnb,
                                                const float2* __restrict__ stats,
                                                __half* __restrict__ oh) {
    __shared__ float T[32][33];
    const int p0 = blockIdx.x * 32, c0 = blockIdx.y * 32, b = blockIdx.z;
    const int t = threadIdx.x;
    {
        int cl = t >> 3, p4 = (t & 7) * 4;
        size_t gidx = ((size_t)b * CCH + c0 + cl) * HW + p0 + p4;
        uint2 hv2 = *reinterpret_cast<const uint2*>(in + gidx);
        const __half2* hp = reinterpret_cast<const __half2*>(&hv2);
        float2 f0 = __half22float2(hp[0]);
        float2 f1 = __half22float2(hp[1]);
        float4 v = make_float4(f0.x, f0.y, f1.x, f1.y);
        float2 st = stats[b];
        size_t widx = (size_t)(c0 + cl) * HW + p0 + p4;
        float4 wv = *reinterpret_cast<const float4*>(lnw + widx);
        float4 bv = *reinterpret_cast<const float4*>(lnb + widx);
        v.x = (v.x - st.x) * st.y * wv.x + bv.x;
        v.y = (v.y - st.x) * st.y * wv.y + bv.y;
        v.z = (v.z - st.x) * st.y * wv.z + bv.z;
        v.w = (v.w - st.x) * st.y * wv.w + bv.w;
        T[cl][p4 + 0] = v.x; T[cl][p4 + 1] = v.y; T[cl][p4 + 2] = v.z; T[cl][p4 + 3] = v.w;
    }
    __syncthreads();
    {
        int pl = t >> 3, c4 = (t & 7) * 4;
        unsigned short hb[4];
        #pragma unroll
        for (int j = 0; j < 4; j++) {
            __half hv = __float2half_rn(T[c4 + j][pl]);
            hb[j] = *reinterpret_cast<unsigned short*>(&hv);
        }
        uint2 pk;
        pk.x = (unsigned int)hb[0] | ((unsigned int)hb[1] << 16);
        pk.y = (unsigned int)hb[2] | ((unsigned int)hb[3] << 16);
        size_t o = ((size_t)b * HW + p0 + pl) * CCH + c0 + c4;
        *reinterpret_cast<uint2*>(oh + o) = pk;
    }
}

// ================= HMMA fp16 GEMM (mma.sync, cp.async 4-stage, 2 CTA/SM) =================
// EPI 1: +bias+aux -> fp16 R (OutH) + LN partial sums
// EPI 2: gelu(+bias) -> fp16 pixel-major
// EPI 5: exp(+bias) if m0<1024 else +bias (QKV, fp32)
// EPI 6: ln2(auxh)+bias+acc -> fp32 (fused LayerNorm residual epilogue for ff2)
#define GSTAGE 20480
template <int EPI>
__global__ __launch_bounds__(256, 2)
void hmma_gemm(const __half* __restrict__ wh,
               const __half* __restrict__ ah,
               const float* __restrict__ bias, const float* __restrict__ aux,
               const __half* __restrict__ auxh,
               float* __restrict__ Out, __half* __restrict__ OutH,
               float2* __restrict__ part,
               const float* __restrict__ lnw, const float* __restrict__ lnb,
               const float2* __restrict__ stats, int K, int M) {
    extern __shared__ unsigned char smem_raw[];
    const uint32_t sb0 = smem_u32(smem_raw);

    const int tid = threadIdx.x;
    const int lane = tid & 31, wid = tid >> 5;
    const int wm = wid & 3, wn = wid >> 2;
    const int n0 = blockIdx.x * 128, m0 = blockIdx.y * 128, b = blockIdx.z;

    const __half* A0 = wh + (size_t)m0 * K;
    const __half* B0 = ah + ((size_t)b * HW + n0) * K;

    const int r0 = tid >> 2, c0c = tid & 3;
    const int r1 = (tid + 256) >> 2;
    const uint32_t s0 = (uint32_t)(r0 * 80 + c0c * 16);
    const uint32_t s1 = (uint32_t)(r1 * 80 + c0c * 16);
    const size_t g0 = (size_t)r0 * K + c0c * 8;
    const size_t g1 = (size_t)r1 * K + c0c * 8;

    const uint32_t aoff = (uint32_t)((wm * 32 + (lane & 15)) * 80 + (lane >> 4) * 16);
    const uint32_t boff = (uint32_t)(10240 +
        (wn * 64 + (lane & 7) + ((lane >> 4) << 3)) * 80 + ((lane >> 3) & 1) * 16);

    float acc[2][8][4];
    #pragma unroll
    for (int i = 0; i < 2; i++)
        #pragma unroll
        for (int j = 0; j < 8; j++)
            #pragma unroll
            for (int q = 0; q < 4; q++) acc[i][j][q] = 0.f;

    const int NIT = K >> 5;

    #pragma unroll
    for (int s = 0; s < 3; s++) {
        uint32_t sbs = sb0 + s * GSTAGE;
        size_t k0 = (size_t)s * 32;
        cp16(sbs + s0,         A0 + g0 + k0);  cp16(sbs + s1,         A0 + g1 + k0);
        cp16(sbs + 10240 + s0, B0 + g0 + k0);  cp16(sbs + 10240 + s1, B0 + g1 + k0);
        cp_commit();
    }

    for (int it = 0; it < NIT; it++) {
        cp_wait<2>();
        __syncthreads();

        if (it + 3 < NIT) {
            int ls = (it + 3) & 3;
            uint32_t sbs = sb0 + ls * GSTAGE;
            size_t k0 = (size_t)(it + 3) * 32;
            cp16(sbs + s0,         A0 + g0 + k0);  cp16(sbs + s1,         A0 + g1 + k0);
            cp16(sbs + 10240 + s0, B0 + g0 + k0);  cp16(sbs + 10240 + s1, B0 + g1 + k0);
        }
        cp_commit();

        const uint32_t sbs = sb0 + (it & 3) * GSTAGE;
        #pragma unroll
        for (int kk = 0; kk < 2; kk++) {
            const uint32_t kb = kk * 32;
            uint32_t ra[2][4], rb[4][4];
            #pragma unroll
            for (int mi = 0; mi < 2; mi++)
                ldm_x4(ra[mi], sbs + aoff + mi * 1280 + kb);
            #pragma unroll
            for (int ni = 0; ni < 4; ni++)
                ldm_x4(rb[ni], sbs + boff + ni * 1280 + kb);
            #pragma unroll
            for (int mi = 0; mi < 2; mi++)
                #pragma unroll
                for (int ni = 0; ni < 4; ni++)
                    #pragma unroll
                    for (int j = 0; j < 2; j++)
                        mma_f16(acc[mi][ni * 2 + j], ra[mi], &rb[ni][j * 2]);
        }
    }

    if (EPI == 2) {
        cp_wait<0>();
        __syncthreads();
        unsigned short* T = reinterpret_cast<unsigned short*>(smem_raw);   // [128][144]
        const int lm0 = wm * 32 + (lane >> 2);
        const int ln0 = wn * 64 + (lane & 3) * 2;
        #pragma unroll
        for (int mi = 0; mi < 2; mi++) {
            const int mA = lm0 + mi * 16;
            const float bv0 = __ldg(bias + m0 + mA);
            const float bv1 = __ldg(bias + m0 + mA + 8);
            #pragma unroll
            for (int nf = 0; nf < 8; nf++) {
                const int n = ln0 + nf * 8;
                float v0 = acc[mi][nf][0] + bv0;
                float v1 = acc[mi][nf][1] + bv0;
                float v2 = acc[mi][nf][2] + bv1;
                float v3 = acc[mi][nf][3] + bv1;
                v0 = 0.5f * v0 * (1.0f + erff(v0 * 0.70710678118654752f));
                v1 = 0.5f * v1 * (1.0f + erff(v1 * 0.70710678118654752f));
                v2 = 0.5f * v2 * (1.0f + erff(v2 * 0.70710678118654752f));
                v3 = 0.5f * v3 * (1.0f + erff(v3 * 0.70710678118654752f));
                __half h0 = __float2half_rn(v0), h1 = __float2half_rn(v1);
                __half h2 = __float2half_rn(v2), h3 = __float2half_rn(v3);
                T[n * 144 + mA]           = *reinterpret_cast<unsigned short*>(&h0);
                T[(n + 1) * 144 + mA]     = *reinterpret_cast<unsigned short*>(&h1);
                T[n * 144 + mA + 8]       = *reinterpret_cast<unsigned short*>(&h2);
                T[(n + 1) * 144 + mA + 8] = *reinterpret_cast<unsigned short*>(&h3);
            }
        }
        __syncthreads();
        #pragma unroll
        for (int i = 0; i < 8; i++) {
            int cc = tid + i * 256;
            int row = cc >> 4, cq = cc & 15;
            uint4 v = *reinterpret_cast<const uint4*>(T + row * 144 + cq * 8);
            size_t o = ((size_t)b * HW + n0 + row) * (size_t)M + m0 + cq * 8;
            *reinterpret_cast<uint4*>(OutH + o) = v;
        }
    } else {
        const bool doexp = (EPI == 5) && (m0 < 1024);
        const int mrow = m0 + wm * 32 + (lane >> 2);
        const int ncol = n0 + wn * 64 + (lane & 3) * 2;
        float ls = 0.f, lq = 0.f;
        float2 st;
        if (EPI == 6) st = stats[b];
        #pragma unroll
        for (int mi = 0; mi < 2; mi++) {
            const int mA = mrow + mi * 16;
            const float bv0 = __ldg(bias + mA);
            const float bv1 = __ldg(bias + mA + 8);
            #pragma unroll
            for (int nf = 0; nf < 8; nf++) {
                const int n = ncol + nf * 8;
                size_t iA = ((size_t)b * M + mA) * HW + n;
                size_t iB = iA + (size_t)8 * HW;
                float2 v0 = make_float2(acc[mi][nf][0] + bv0, acc[mi][nf][1] + bv0);
                float2 v1 = make_float2(acc[mi][nf][2] + bv1, acc[mi][nf][3] + bv1);
                if (EPI == 5) {
                    if (doexp) {
                        v0.x = fexp(v0.x); v0.y = fexp(v0.y);
                        v1.x = fexp(v1.x); v1.y = fexp(v1.y);
                    }
                    *reinterpret_cast<float2*>(Out + iA) = v0;
                    *reinterpret_cast<float2*>(Out + iB) = v1;
                } else if (EPI == 1) {
                    float2 a0 = *reinterpret_cast<const float2*>(aux + iA);
                    float2 a1 = *reinterpret_cast<const float2*>(aux + iB);
                    v0.x += a0.x; v0.y += a0.y; v1.x += a1.x; v1.y += a1.y;
                    ls += v0.x + v0.y + v1.x + v1.y;
                    lq += v0.x * v0.x + v0.y * v0.y + v1.x * v1.x + v1.y * v1.y;
                    *reinterpret_cast<__half2*>(OutH + iA) = __floats2half2_rn(v0.x, v0.y);
                    *reinterpret_cast<__half2*>(OutH + iB) = __floats2half2_rn(v1.x, v1.y);
                } else if (EPI == 6) {
                    // fused LN2: out = ln2(Rh) + acc + bias
                    size_t wA = (size_t)mA * HW + n;
                    size_t wB = wA + (size_t)8 * HW;
                    float2 r0 = __half22float2(*reinterpret_cast<const __half2*>(auxh + iA));
                    float2 r1 = __half22float2(*reinterpret_cast<const __half2*>(auxh + iB));
                    float2 w0 = *reinterpret_cast<const float2*>(lnw + wA);
                    float2 w1 = *reinterpret_cast<const float2*>(lnw + wB);
                    float2 l0 = *reinterpret_cast<const float2*>(lnb + wA);
                    float2 l1 = *reinterpret_cast<const float2*>(lnb + wB);
                    v0.x += (r0.x - st.x) * st.y * w0.x + l0.x;
                    v0.y += (r0.y - st.x) * st.y * w0.y + l0.y;
                    v1.x += (r1.x - st.x) * st.y * w1.x + l1.x;
                    v1.y += (r1.y - st.x) * st.y * w1.y + l1.y;
                    *reinterpret_cast<float2*>(Out + iA) = v0;
                    *reinterpret_cast<float2*>(Out + iB) = v1;
                }
            }
        }
        if (EPI == 1) {
            ls = bred_sum(ls);
            lq = bred_sum(lq);
            if (tid == 0)
                part[b * 128 + blockIdx.y * 32 + blockIdx.x] = make_float2(ls, lq);
        }
    }
}

// ===== qsum: per-pixel sum over 512 channels of expQ =====
__global__ __launch_bounds__(256) void colsum(const float* __restrict__ QKV,
                                              float* __restrict__ qsum) {
    int gid = blockIdx.x * 256 + threadIdx.x;
    int b = gid >> 12, pix = gid & 4095;
    const float* base = QKV + (size_t)b * 3 * PERB + pix;
    float s = 0.f;
    #pragma unroll 8
    for (int c = 0; c < CCH; c++) s += base[(size_t)c * HW];
    qsum[gid] = s;
}

// ================= attention =================
__global__ __launch_bounds__(256) void kv_part(const float* __restrict__ QKV,
                                               float* __restrict__ KVp,
                                               float* __restrict__ ksp) {
    const int cx = blockIdx.x;
    const int bh = blockIdx.y;
    const int b = bh >> 3, h = bh & 7;
    const float* Kb = QKV + (size_t)b * 3 * PERB + PERB     + (size_t)h * HDIM * HW;
    const float* Vb = QKV + (size_t)b * 3 * PERB + 2 * PERB + (size_t)h * HDIM * HW;
    __shared__ float Ks[64][65];
    __shared__ float Vs[64][65];
    const int tid = threadIdx.x;
    const int tx = tid & 15, ty = tid >> 4;
    float acc[4][4] = {};
    float ksloc[4] = {0.f, 0.f, 0.f, 0.f};
    const int pbeg = cx * 512, pend = pbeg + 512;
    for (int p0 = pbeg; p0 < pend; p0 += 64) {
        #pragma unroll
        for (int t = 0; t < 4; t++) {
            int lin = tid + t * 256;
            int r = lin >> 4, c4 = (lin & 15) * 4;
            float4 kv4 = *reinterpret_cast<const float4*>(&Kb[(size_t)r * HW + p0 + c4]);
            float4 vv4 = *reinterpret_cast<const float4*>(&Vb[(size_t)r * HW + p0 + c4]);
            ksloc[t] += kv4.x + kv4.y + kv4.z + kv4.w;
            Ks[r][c4 + 0] = kv4.x; Ks[r][c4 + 1] = kv4.y; Ks[r][c4 + 2] = kv4.z; Ks[r][c4 + 3] = kv4.w;
            Vs[r][c4 + 0] = vv4.x; Vs[r][c4 + 1] = vv4.y; Vs[r][c4 + 2] = vv4.z; Vs[r][c4 + 3] = vv4.w;
        }
        __syncthreads();
        #pragma unroll 8
        for (int p = 0; p < 64; p++) {
            float ra[4], rb[4];
            #pragma unroll
            for (int i = 0; i < 4; i++) ra[i] = Ks[ty * 4 + i][p];
            #pragma unroll
            for (int j = 0; j < 4; j++) rb[j] = Vs[tx * 4 + j][p];
            #pragma unroll
            for (int i = 0; i < 4; i++)
                #pragma unroll
                for (int j = 0; j < 4; j++)
                    acc[i][j] = fmaf(ra[i], rb[j], acc[i][j]);
        }
        __syncthreads();
    }
    #pragma unroll
    for (int t = 0; t < 4; t++) {
        float v = ksloc[t];
        #pragma unroll
        for (int o = 8; o; o >>= 1) v += __shfl_down_sync(0xffffffffu, v, o, 16);
        if ((tid & 15) == 0)
            ksp[((size_t)cx * 128 + bh) * HDIM + (tid >> 4) + 16 * t] = v;
    }
    float* out = KVp + ((size_t)cx * 128 + bh) * (HDIM * HDIM);
    #pragma unroll
    for (int i = 0; i < 4; i++)
        #pragma unroll
        for (int j = 0; j < 4; j++)
            out[(ty * 4 + i) * HDIM + tx * 4 + j] = acc[i][j];
}
__global__ __launch_bounds__(256) void kv_reduce(const float* __restrict__ KVp,
                                                 const float* __restrict__ ksp,
                                                 float* __restrict__ KV) {
    __shared__ float kinv_s[HDIM];
    const int bh = blockIdx.x;
    if (threadIdx.x < HDIM) {
        float s = 0.f;
        #pragma unroll
        for (int cx = 0; cx < 8; cx++)
            s += ksp[((size_t)cx * 128 + bh) * HDIM + threadIdx.x];
        kinv_s[threadIdx.x] = 1.f / s;
    }
    __syncthreads();
    #pragma unroll
    for (int t = 0; t < 16; t++) {
        int e = threadIdx.x + t * 256;
        float s = 0.f;
        #pragma unroll
        for (int cx = 0; cx < 8; cx++)
            s += KVp[((size_t)cx * 128 + bh) * (HDIM * HDIM) + e];
        KV[(size_t)bh * HDIM * HDIM + e] = s * kinv_s[e >> 6];
    }
}
__global__ __launch_bounds__(256) void attn_kernel(const float* __restrict__ KV,
                                                   const float* __restrict__ QKV,
                                                   const float* __restrict__ qsum,
                                                   __half* __restrict__ Th) {
    const int bh = blockIdx.y;
    const int p0 = blockIdx.x * 64;
    const int b = bh >> 3, h = bh & 7;
    const float* Qb  = QKV + (size_t)b * 3 * PERB + (size_t)h * HDIM * HW;
    const float* KVb = KV + (size_t)bh * HDIM * HDIM;
    __shared__ float KVs[64][64];
    __shared__ float Qs[64][68];
    __shared__ unsigned short TT[64][72];
    const int tid = threadIdx.x;
    const int tx = tid & 15, ty = tid >> 4;
    #pragma unroll
    for (int t = 0; t < 4; t++) {
        int lin = tid + t * 256;
        int r = lin >> 4, c4 = (lin & 15) * 4;
        *reinterpret_cast<float4*>(&KVs[r][c4]) =
            *reinterpret_cast<const float4*>(&KVb[(size_t)r * HDIM + c4]);
        float4 q4 = *reinterpret_cast<const float4*>(&Qb[(size_t)r * HW + p0 + c4]);
        *reinterpret_cast<float4*>(&Qs[r][c4]) = q4;
    }
    __syncthreads();
    float acc[4][4] = {};
    #pragma unroll 8
    for (int k = 0; k < 64; k++) {
        float4 q4 = *reinterpret_cast<const float4*>(&Qs[k][tx * 4]);
        float4 a4 = *reinterpret_cast<const float4*>(&KVs[k][ty * 4]);
        float ra[4] = {a4.x, a4.y, a4.z, a4.w};
        float rb[4] = {q4.x, q4.y, q4.z, q4.w};
        #pragma unroll
        for (int i = 0; i < 4; i++)
            #pragma unroll
            for (int j = 0; j < 4; j++)
                acc[i][j] = fmaf(ra[i], rb[j], acc[i][j]);
    }
    const int bq = b * HW + p0 + tx * 4;
    float inv[4];
    #pragma unroll
    for (int j = 0; j < 4; j++) inv[j] = 1.f / qsum[bq + j];
    #pragma unroll
    for (int i = 0; i < 4; i++)
        #pragma unroll
        for (int j = 0; j < 4; j++) {
            __half hv = __float2half_rn(acc[i][j] * inv[j]);
            TT[tx * 4 + j][ty * 4 + i] = *reinterpret_cast<unsigned short*>(&hv);
        }
    __syncthreads();
    #pragma unroll
    for (int t = 0; t < 2; t++) {
        int cc = tid + t * 256;
        int p = cc >> 3, co = (cc & 7) * 8;
        uint4 v = *reinterpret_cast<const uint4*>(&TT[p][co]);
        size_t o = ((size_t)b * HW + p0 + p) * CCH + h * 64 + co;
        *reinterpret_cast<uint4*>(Th + o) = v;
    }
}

// ================= launch =================
extern "C" void kernel_launch(void* const* d_in, const int* in_sizes, int n_in,
                              void* d_out, int out_size) {
    const float* x     = (const float*)d_in[0];
    const float* ln1w  = (const float*)d_in[1];
    const float* ln1b  = (const float*)d_in[2];
    const float* qw    = (const float*)d_in[3];
    const float* qb    = (const float*)d_in[4];
    const float* kw    = (const float*)d_in[5];
    const float* kb    = (const float*)d_in[6];
    const float* vw    = (const float*)d_in[7];
    const float* vb    = (const float*)d_in[8];
    const float* huw   = (const float*)d_in[9];
    const float* hub   = (const float*)d_in[10];
    const float* ln2w  = (const float*)d_in[11];
    const float* ln2b  = (const float*)d_in[12];
    const float* ff1w  = (const float*)d_in[13];
    const float* ff1b  = (const float*)d_in[14];
    const float* ff2w  = (const float*)d_in[15];
    const float* ff2b  = (const float*)d_in[16];
    float* out = (float*)d_out;

    float *QKV, *KVp, *ksp, *KV, *qsum, *bqkv;
    float2 *part, *stats;
    __half *Rh, *Th, *Fh, *Wh;
    cudaGetSymbolAddress((void**)&QKV, g_QKV);
    cudaGetSymbolAddress((void**)&Rh, g_Rh);
    cudaGetSymbolAddress((void**)&KVp, g_KVp);
    cudaGetSymbolAddress((void**)&ksp, g_ksp);
    cudaGetSymbolAddress((void**)&KV, g_KV);
    cudaGetSymbolAddress((void**)&qsum, g_qsum);
    cudaGetSymbolAddress((void**)&bqkv, g_bqkv);
    cudaGetSymbolAddress((void**)&part, g_part);
    cudaGetSymbolAddress((void**)&stats, g_stats);
    cudaGetSymbolAddress((void**)&Th, g_Th);
    cudaGetSymbolAddress((void**)&Fh, g_Fh);
    cudaGetSymbolAddress((void**)&Wh, g_Wh);

    const int SMEM = 4 * GSTAGE;   // 81920
    cudaFuncSetAttribute(hmma_gemm<1>, cudaFuncAttributeMaxDynamicSharedMemorySize, SMEM);
    cudaFuncSetAttribute(hmma_gemm<2>, cudaFuncAttributeMaxDynamicSharedMemorySize, SMEM);
    cudaFuncSetAttribute(hmma_gemm<5>, cudaFuncAttributeMaxDynamicSharedMemorySize, SMEM);
    cudaFuncSetAttribute(hmma_gemm<6>, cudaFuncAttributeMaxDynamicSharedMemorySize, SMEM);

    const dim3 gT(HW / 32, CCH / 32, BATCH);         // (128, 16, 16)
    const dim3 gQKVg(HW / 128, 1536 / 128, BATCH);   // (32, 12, 16)
    const dim3 gG512(HW / 128, CCH / 128, BATCH);    // (32, 4, 16)
    const dim3 gG2048(HW / 128, DHID / 128, BATCH);  // (32, 16, 16)

    // weights + bias (one launch)
    wconv_all<<<(WTOT + 1536) / 256, 256>>>(qw, kw, vw, huw, ff1w, ff2w, qb, kb, vb, Wh, bqkv);

    // ln1 -> Th
    ln_stats<<<dim3(128, BATCH), 256>>>(x, part);
    ln_finalize<<<BATCH, 128>>>(part, stats);
    conv_t<<<gT, 256>>>(x, ln1w, ln1b, stats, Th);

    // fused QKV GEMM (fp32 out, exp fused for Q/K rows)
    hmma_gemm<5><<<gQKVg, 256, SMEM>>>(Wh, Th, bqkv, nullptr, nullptr, QKV, nullptr, nullptr,
                                       nullptr, nullptr, nullptr, CCH, 1536);

    colsum<<<(BATCH * HW) / 256, 256>>>(QKV, qsum);

    kv_part<<<dim3(8, 128), 256>>>(QKV, KVp, ksp);
    kv_reduce<<<128, 256>>>(KVp, ksp, KV);
    attn_kernel<<<dim3(HW / 64, BATCH * NHEAD), 256>>>(KV, QKV, qsum, Th);

    // Rh = fp16(x + hu(attn)); LN2 partials fused
    hmma_gemm<1><<<gG512, 256, SMEM>>>(Wh + WOFF_HU, Th, hub, x, nullptr, nullptr, Rh, part,
                                       nullptr, nullptr, nullptr, CCH, CCH);
    ln_finalize<<<BATCH, 128>>>(part, stats);

    // ln2(Rh) -> Th
    conv_t_h<<<gT, 256>>>(Rh, ln2w, ln2b, stats, Th);

    // Fh = fp16(gelu(ff1)); out = ln2(Rh) + ff2(Fh)  [fused epilogue]
    hmma_gemm<2><<<gG2048, 256, SMEM>>>(Wh + WOFF_FF1, Th, ff1b, nullptr, nullptr, nullptr, Fh,
                                        nullptr, nullptr, nullptr, nullptr, CCH, DHID);
    hmma_gemm<6><<<gG512, 256, SMEM>>>(Wh + WOFF_FF2, Fh, ff2b, nullptr, Rh, out, nullptr,
                                       nullptr, ln2w, ln2b, stats, DHID, CCH);
}

// round 16
// speedup vs baseline: 1.0402x; 1.0005x over previous
#include <cuda_runtime.h>
#include <cuda_fp16.h>
#include <math.h>
#include <stdint.h>

// ---------------- problem constants ----------------
#define BATCH 16
#define CCH   512
#define HW    4096
#define DHID  2048
#define NHEAD 8
#define HDIM  64
#define PERB  (CCH*HW)
#define LN_EPS 1e-5f

// ---------------- device scratch (allocation-free) ----------------
__device__ float g_QKV[(size_t)BATCH*3*PERB];   // (b,1536,HW): rows 512-1023 expK, 1024-1535 V (Q slot unused)
__device__ __half g_Qh[(size_t)BATCH*PERB];     // expQ fp16 channel-major (b,512,HW)
__device__ __half g_Rh[BATCH*PERB];             // residual R = x + hu(attn), fp16
__device__ float g_KVp[8*128*HDIM*HDIM];        // split-K partials
__device__ float g_ksp[8*128*HDIM];             // split-K row-sum partials of expK
__device__ float g_KV [BATCH*NHEAD*HDIM*HDIM];
__device__ float g_qsum[BATCH*HW];
__device__ float g_bqkv[3*CCH];
__device__ float2 g_part[BATCH*128];
__device__ float2 g_stats[BATCH];
// fp16 activations pixel-major (b, p, c)
__device__ __half g_Th[(size_t)BATCH*HW*CCH];
__device__ __half g_Fh[(size_t)BATCH*HW*DHID];
// fp16 weights (stacked: q,k,v,hu,ff1,ff2)
#define WOFF_HU  786432
#define WOFF_FF1 1048576
#define WOFF_FF2 2097152
#define WTOT     3145728
__device__ __half g_Wh[WTOT];

// ================= PTX helpers =================
__device__ __forceinline__ uint32_t smem_u32(const void* p) {
    uint32_t a;
    asm("{ .reg .u64 t; cvta.to.shared.u64 t, %1; cvt.u32.u64 %0, t; }" : "=r"(a) : "l"(p));
    return a;
}
__device__ __forceinline__ void cp16(uint32_t dst, const void* src) {
    asm volatile("cp.async.cg.shared.global [%0], [%1], 16;" :: "r"(dst), "l"(src));
}
__device__ __forceinline__ void cp_commit() {
    asm volatile("cp.async.commit_group;" ::: "memory");
}
template <int N>
__device__ __forceinline__ void cp_wait() {
    asm volatile("cp.async.wait_group %0;" :: "n"(N) : "memory");
}
__device__ __forceinline__ void ldm_x4(uint32_t* r, uint32_t addr) {
    asm volatile("ldmatrix.sync.aligned.m8n8.x4.shared.b16 {%0,%1,%2,%3}, [%4];"
                 : "=r"(r[0]), "=r"(r[1]), "=r"(r[2]), "=r"(r[3]) : "r"(addr));
}
__device__ __forceinline__ void mma_f16(float* c, const uint32_t* a, const uint32_t* b) {
    asm("mma.sync.aligned.m16n8k16.row.col.f32.f16.f16.f32 "
        "{%0,%1,%2,%3}, {%4,%5,%6,%7}, {%8,%9}, {%0,%1,%2,%3};"
        : "+f"(c[0]), "+f"(c[1]), "+f"(c[2]), "+f"(c[3])
        : "r"(a[0]), "r"(a[1]), "r"(a[2]), "r"(a[3]), "r"(b[0]), "r"(b[1]));
}

// fast exp on FMA pipe
__device__ __forceinline__ float fexp(float x) {
    float t = x * 1.4426950408889634f;
    float n = rintf(t);
    float r = t - n;
    float p = 0.00015403530393381609f;
    p = fmaf(p, r, 0.0013333558146428443f);
    p = fmaf(p, r, 0.009618129107628477f);
    p = fmaf(p, r, 0.05550410866482158f);
    p = fmaf(p, r, 0.2402265069591007f);
    p = fmaf(p, r, 0.6931471805599453f);
    p = fmaf(p, r, 1.0f);
    int e = __float2int_rn(n);
    return p * __int_as_float((e + 127) << 23);
}

// ================= block reductions =================
__device__ __forceinline__ float bred_sum(float v) {
    __shared__ float sb[8];
    int lane = threadIdx.x & 31, w = threadIdx.x >> 5;
    #pragma unroll
    for (int o = 16; o; o >>= 1) v += __shfl_down_sync(0xffffffffu, v, o);
    if (lane == 0) sb[w] = v;
    __syncthreads();
    if (threadIdx.x < 32) {
        float r = (lane < 8) ? sb[lane] : 0.f;
        #pragma unroll
        for (int o = 4; o; o >>= 1) r += __shfl_down_sync(0xffffffffu, r, o);
        if (lane == 0) sb[0] = r;
    }
    __syncthreads();
    float out = sb[0];
    __syncthreads();
    return out;
}

// ================= weight conversion + bias pack (one launch) =================
__global__ __launch_bounds__(256) void wconv_all(const float* __restrict__ qw,
                                                 const float* __restrict__ kw,
                                                 const float* __restrict__ vw,
                                                 const float* __restrict__ huw,
                                                 const float* __restrict__ ff1w,
                                                 const float* __restrict__ ff2w,
                                                 const float* __restrict__ qb,
                                                 const float* __restrict__ kb,
                                                 const float* __restrict__ vb,
                                                 __half* __restrict__ h,
                                                 float* __restrict__ bq) {
    int i = blockIdx.x * 256 + threadIdx.x;
    if (i < WTOT) {
        float v;
        if (i < 786432) {
            int seg = i >> 18, off = i & 262143;
            v = (seg == 0) ? qw[off] : (seg == 1) ? kw[off] : vw[off];
        } else if (i < 1048576) {
            v = huw[i - 786432];
        } else if (i < 2097152) {
            v = ff1w[i - 1048576];
        } else {
            v = ff2w[i - 2097152];
        }
        h[i] = __float2half_rn(v);
    } else {
        int j = i - WTOT;
        if (j < 512) bq[j] = qb[j];
        else if (j < 1024) bq[j] = kb[j - 512];
        else if (j < 1536) bq[j] = vb[j - 1024];
    }
}

// ================= LayerNorm stats =================
__global__ __launch_bounds__(256) void ln_stats(const float* __restrict__ in,
                                                float2* __restrict__ part) {
    int b = blockIdx.y, pb = blockIdx.x;
    const float* p = in + (size_t)b * PERB + (size_t)pb * 16384;
    float s = 0.f, q = 0.f;
    #pragma unroll
    for (int i = 0; i < 16; i++) {
        float4 v = *reinterpret_cast<const float4*>(p + (size_t)(threadIdx.x + i * 256) * 4);
        s += v.x + v.y + v.z + v.w;
        q += v.x * v.x + v.y * v.y + v.z * v.z + v.w * v.w;
    }
    s = bred_sum(s);
    q = bred_sum(q);
    if (threadIdx.x == 0) part[b * 128 + pb] = make_float2(s, q);
}
__global__ __launch_bounds__(128) void ln_finalize(const float2* __restrict__ part,
                                                   float2* __restrict__ stats) {
    __shared__ double ss[128], qq[128];
    const int b = blockIdx.x, t = threadIdx.x;
    float2 p = part[b * 128 + t];
    ss[t] = (double)p.x;
    qq[t] = (double)p.y;
    __syncthreads();
    #pragma unroll
    for (int o = 64; o; o >>= 1) {
        if (t < o) { ss[t] += ss[t + o]; qq[t] += qq[t + o]; }
        __syncthreads();
    }
    if (t == 0) {
        double invN = 1.0 / (double)PERB;
        double mu = ss[0] * invN;
        double var = qq[0] * invN - mu * mu;
        double rstd = 1.0 / sqrt(var + (double)LN_EPS);
        stats[b] = make_float2((float)mu, (float)rstd);
    }
}

// ===== conv_t: fp32 (b,512,HW) -> LN -> fp16 (b,HW,512) =====
__global__ __launch_bounds__(256) void conv_t(const float* __restrict__ in,
                                              const float* __restrict__ lnw,
                                              const float* __restrict__ lnb,
                                              const float2* __restrict__ stats,
                                              __half* __restrict__ oh) {
    __shared__ float T[32][33];
    const int p0 = blockIdx.x * 32, c0 = blockIdx.y * 32, b = blockIdx.z;
    const int t = threadIdx.x;
    {
        int cl = t >> 3, p4 = (t & 7) * 4;
        size_t gidx = ((size_t)b * CCH + c0 + cl) * HW + p0 + p4;
        float4 v = *reinterpret_cast<const float4*>(in + gidx);
        float2 st = stats[b];
        size_t widx = (size_t)(c0 + cl) * HW + p0 + p4;
        float4 wv = *reinterpret_cast<const float4*>(lnw + widx);
        float4 bv = *reinterpret_cast<const float4*>(lnb + widx);
        v.x = (v.x - st.x) * st.y * wv.x + bv.x;
        v.y = (v.y - st.x) * st.y * wv.y + bv.y;
        v.z = (v.z - st.x) * st.y * wv.z + bv.z;
        v.w = (v.w - st.x) * st.y * wv.w + bv.w;
        T[cl][p4 + 0] = v.x; T[cl][p4 + 1] = v.y; T[cl][p4 + 2] = v.z; T[cl][p4 + 3] = v.w;
    }
    __syncthreads();
    {
        int pl = t >> 3, c4 = (t & 7) * 4;
        unsigned short hb[4];
        #pragma unroll
        for (int j = 0; j < 4; j++) {
            __half hv = __float2half_rn(T[c4 + j][pl]);
            hb[j] = *reinterpret_cast<unsigned short*>(&hv);
        }
        uint2 pk;
        pk.x = (unsigned int)hb[0] | ((unsigned int)hb[1] << 16);
        pk.y = (unsigned int)hb[2] | ((unsigned int)hb[3] << 16);
        size_t o = ((size_t)b * HW + p0 + pl) * CCH + c0 + c4;
        *reinterpret_cast<uint2*>(oh + o) = pk;
    }
}

// ===== conv_t_h: fp16 R (b,512,HW) -> LN -> fp16 (b,HW,512) =====
__global__ __launch_bounds__(256) void conv_t_h(const __half* __restrict__ in,
                                                const float* __restrict__ lnw,
                                                const float* __restrict__ lnb,
                                                const float2* __restrict__ stats,
                                                __half* __restrict__ oh) {
    __shared__ float T[32][33];
    const int p0 = blockIdx.x * 32, c0 = blockIdx.y * 32, b = blockIdx.z;
    const int t = threadIdx.x;
    {
        int cl = t >> 3, p4 = (t & 7) * 4;
        size_t gidx = ((size_t)b * CCH + c0 + cl) * HW + p0 + p4;
        uint2 hv2 = *reinterpret_cast<const uint2*>(in + gidx);
        const __half2* hp = reinterpret_cast<const __half2*>(&hv2);
        float2 f0 = __half22float2(hp[0]);
        float2 f1 = __half22float2(hp[1]);
        float4 v = make_float4(f0.x, f0.y, f1.x, f1.y);
        float2 st = stats[b];
        size_t widx = (size_t)(c0 + cl) * HW + p0 + p4;
        float4 wv = *reinterpret_cast<const float4*>(lnw + widx);
        float4 bv = *reinterpret_cast<const float4*>(lnb + widx);
        v.x = (v.x - st.x) * st.y * wv.x + bv.x;
        v.y = (v.y - st.x) * st.y * wv.y + bv.y;
        v.z = (v.z - st.x) * st.y * wv.z + bv.z;
        v.w = (v.w - st.x) * st.y * wv.w + bv.w;
        T[cl][p4 + 0] = v.x; T[cl][p4 + 1] = v.y; T[cl][p4 + 2] = v.z; T[cl][p4 + 3] = v.w;
    }
    __syncthreads();
    {
        int pl = t >> 3, c4 = (t & 7) * 4;
        unsigned short hb[4];
        #pragma unroll
        for (int j = 0; j < 4; j++) {
            __half hv = __float2half_rn(T[c4 + j][pl]);
            hb[j] = *reinterpret_cast<unsigned short*>(&hv);
        }
        uint2 pk;
        pk.x = (unsigned int)hb[0] | ((unsigned int)hb[1] << 16);
        pk.y = (unsigned int)hb[2] | ((unsigned int)hb[3] << 16);
        size_t o = ((size_t)b * HW + p0 + pl) * CCH + c0 + c4;
        *reinterpret_cast<uint2*>(oh + o) = pk;
    }
}

// ================= HMMA fp16 GEMM (mma.sync, cp.async 4-stage, 2 CTA/SM) =================
// EPI 1: +bias+aux -> fp16 R (OutH) + LN partial sums
// EPI 2: gelu(+bias) -> fp16 pixel-major
// EPI 5: QKV: m0<512 -> exp -> fp16 Qh (smem-staged); m0<1024 -> exp fp32; else +bias fp32
// EPI 6: ln2(auxh)+bias+acc -> fp32 (fused LayerNorm residual epilogue for ff2)
#define GSTAGE 20480
template <int EPI>
__global__ __launch_bounds__(256, 2)
void hmma_gemm(const __half* __restrict__ wh,
               const __half* __restrict__ ah,
               const float* __restrict__ bias, const float* __restrict__ aux,
               const __half* __restrict__ auxh,
               float* __restrict__ Out, __half* __restrict__ OutH,
               float2* __restrict__ part,
               const float* __restrict__ lnw, const float* __restrict__ lnb,
               const float2* __restrict__ stats, int K, int M) {
    extern __shared__ unsigned char smem_raw[];
    const uint32_t sb0 = smem_u32(smem_raw);

    const int tid = threadIdx.x;
    const int lane = tid & 31, wid = tid >> 5;
    const int wm = wid & 3, wn = wid >> 2;
    const int n0 = blockIdx.x * 128, m0 = blockIdx.y * 128, b = blockIdx.z;

    const __half* A0 = wh + (size_t)m0 * K;
    const __half* B0 = ah + ((size_t)b * HW + n0) * K;

    const int r0 = tid >> 2, c0c = tid & 3;
    const int r1 = (tid + 256) >> 2;
    const uint32_t s0 = (uint32_t)(r0 * 80 + c0c * 16);
    const uint32_t s1 = (uint32_t)(r1 * 80 + c0c * 16);
    const size_t g0 = (size_t)r0 * K + c0c * 8;
    const size_t g1 = (size_t)r1 * K + c0c * 8;

    const uint32_t aoff = (uint32_t)((wm * 32 + (lane & 15)) * 80 + (lane >> 4) * 16);
    const uint32_t boff = (uint32_t)(10240 +
        (wn * 64 + (lane & 7) + ((lane >> 4) << 3)) * 80 + ((lane >> 3) & 1) * 16);

    float acc[2][8][4];
    #pragma unroll
    for (int i = 0; i < 2; i++)
        #pragma unroll
        for (int j = 0; j < 8; j++)
            #pragma unroll
            for (int q = 0; q < 4; q++) acc[i][j][q] = 0.f;

    const int NIT = K >> 5;

    #pragma unroll
    for (int s = 0; s < 3; s++) {
        uint32_t sbs = sb0 + s * GSTAGE;
        size_t k0 = (size_t)s * 32;
        cp16(sbs + s0,         A0 + g0 + k0);  cp16(sbs + s1,         A0 + g1 + k0);
        cp16(sbs + 10240 + s0, B0 + g0 + k0);  cp16(sbs + 10240 + s1, B0 + g1 + k0);
        cp_commit();
    }

    for (int it = 0; it < NIT; it++) {
        cp_wait<2>();
        __syncthreads();

        if (it + 3 < NIT) {
            int ls = (it + 3) & 3;
            uint32_t sbs = sb0 + ls * GSTAGE;
            size_t k0 = (size_t)(it + 3) * 32;
            cp16(sbs + s0,         A0 + g0 + k0);  cp16(sbs + s1,         A0 + g1 + k0);
            cp16(sbs + 10240 + s0, B0 + g0 + k0);  cp16(sbs + 10240 + s1, B0 + g1 + k0);
        }
        cp_commit();

        const uint32_t sbs = sb0 + (it & 3) * GSTAGE;
        #pragma unroll
        for (int kk = 0; kk < 2; kk++) {
            const uint32_t kb = kk * 32;
            uint32_t ra[2][4], rb[4][4];
            #pragma unroll
            for (int mi = 0; mi < 2; mi++)
                ldm_x4(ra[mi], sbs + aoff + mi * 1280 + kb);
            #pragma unroll
            for (int ni = 0; ni < 4; ni++)
                ldm_x4(rb[ni], sbs + boff + ni * 1280 + kb);
            #pragma unroll
            for (int mi = 0; mi < 2; mi++)
                #pragma unroll
                for (int ni = 0; ni < 4; ni++)
                    #pragma unroll
                    for (int j = 0; j < 2; j++)
                        mma_f16(acc[mi][ni * 2 + j], ra[mi], &rb[ni][j * 2]);
        }
    }

    if (EPI == 2) {
        cp_wait<0>();
        __syncthreads();
        unsigned short* T = reinterpret_cast<unsigned short*>(smem_raw);   // [128][144]
        const int lm0 = wm * 32 + (lane >> 2);
        const int ln0 = wn * 64 + (lane & 3) * 2;
        #pragma unroll
        for (int mi = 0; mi < 2; mi++) {
            const int mA = lm0 + mi * 16;
            const float bv0 = __ldg(bias + m0 + mA);
            const float bv1 = __ldg(bias + m0 + mA + 8);
            #pragma unroll
            for (int nf = 0; nf < 8; nf++) {
                const int n = ln0 + nf * 8;
                float v0 = acc[mi][nf][0] + bv0;
                float v1 = acc[mi][nf][1] + bv0;
                float v2 = acc[mi][nf][2] + bv1;
                float v3 = acc[mi][nf][3] + bv1;
                v0 = 0.5f * v0 * (1.0f + erff(v0 * 0.70710678118654752f));
                v1 = 0.5f * v1 * (1.0f + erff(v1 * 0.70710678118654752f));
                v2 = 0.5f * v2 * (1.0f + erff(v2 * 0.70710678118654752f));
                v3 = 0.5f * v3 * (1.0f + erff(v3 * 0.70710678118654752f));
                __half h0 = __float2half_rn(v0), h1 = __float2half_rn(v1);
                __half h2 = __float2half_rn(v2), h3 = __float2half_rn(v3);
                T[n * 144 + mA]           = *reinterpret_cast<unsigned short*>(&h0);
                T[(n + 1) * 144 + mA]     = *reinterpret_cast<unsigned short*>(&h1);
                T[n * 144 + mA + 8]       = *reinterpret_cast<unsigned short*>(&h2);
                T[(n + 1) * 144 + mA + 8] = *reinterpret_cast<unsigned short*>(&h3);
            }
        }
        __syncthreads();
        #pragma unroll
        for (int i = 0; i < 8; i++) {
            int cc = tid + i * 256;
            int row = cc >> 4, cq = cc & 15;
            uint4 v = *reinterpret_cast<const uint4*>(T + row * 144 + cq * 8);
            size_t o = ((size_t)b * HW + n0 + row) * (size_t)M + m0 + cq * 8;
            *reinterpret_cast<uint4*>(OutH + o) = v;
        }
    } else if (EPI == 5 && m0 < 512) {
        // Q rows: exp(+bias) -> fp16 channel-major via smem staging (coalesced)
        cp_wait<0>();
        __syncthreads();
        unsigned short* T = reinterpret_cast<unsigned short*>(smem_raw);   // [128][136]
        const int lm0 = wm * 32 + (lane >> 2);
        const int ln0 = wn * 64 + (lane & 3) * 2;
        #pragma unroll
        for (int mi = 0; mi < 2; mi++) {
            const int mA = lm0 + mi * 16;
            const float bv0 = __ldg(bias + m0 + mA);
            const float bv1 = __ldg(bias + m0 + mA + 8);
            #pragma unroll
            for (int nf = 0; nf < 8; nf++) {
                const int n = ln0 + nf * 8;
                float v0 = fexp(acc[mi][nf][0] + bv0);
                float v1 = fexp(acc[mi][nf][1] + bv0);
                float v2 = fexp(acc[mi][nf][2] + bv1);
                float v3 = fexp(acc[mi][nf][3] + bv1);
                *reinterpret_cast<__half2*>(T + mA * 136 + n)       = __floats2half2_rn(v0, v1);
                *reinterpret_cast<__half2*>(T + (mA + 8) * 136 + n) = __floats2half2_rn(v2, v3);
            }
        }
        __syncthreads();
        #pragma unroll
        for (int i = 0; i < 8; i++) {
            int cc = tid + i * 256;            // 2048 chunks: 128 rows x 16 chunks
            int row = cc >> 4, cq = cc & 15;
            uint4 v = *reinterpret_cast<const uint4*>(T + row * 136 + cq * 8);
            size_t o = ((size_t)b * CCH + m0 + row) * HW + n0 + cq * 8;
            *reinterpret_cast<uint4*>(OutH + o) = v;
        }
    } else {
        const bool doexp = (EPI == 5) && (m0 < 1024);
        const int mrow = m0 + wm * 32 + (lane >> 2);
        const int ncol = n0 + wn * 64 + (lane & 3) * 2;
        float ls = 0.f, lq = 0.f;
        float2 st;
        if (EPI == 6) st = stats[b];
        #pragma unroll
        for (int mi = 0; mi < 2; mi++) {
            const int mA = mrow + mi * 16;
            const float bv0 = __ldg(bias + mA);
            const float bv1 = __ldg(bias + mA + 8);
            #pragma unroll
            for (int nf = 0; nf < 8; nf++) {
                const int n = ncol + nf * 8;
                size_t iA = ((size_t)b * M + mA) * HW + n;
                size_t iB = iA + (size_t)8 * HW;
                float2 v0 = make_float2(acc[mi][nf][0] + bv0, acc[mi][nf][1] + bv0);
                float2 v1 = make_float2(acc[mi][nf][2] + bv1, acc[mi][nf][3] + bv1);
                if (EPI == 5) {
                    if (doexp) {
                        v0.x = fexp(v0.x); v0.y = fexp(v0.y);
                        v1.x = fexp(v1.x); v1.y = fexp(v1.y);
                    }
                    *reinterpret_cast<float2*>(Out + iA) = v0;
                    *reinterpret_cast<float2*>(Out + iB) = v1;
                } else if (EPI == 1) {
                    float2 a0 = *reinterpret_cast<const float2*>(aux + iA);
                    float2 a1 = *reinterpret_cast<const float2*>(aux + iB);
                    v0.x += a0.x; v0.y += a0.y; v1.x += a1.x; v1.y += a1.y;
                    ls += v0.x + v0.y + v1.x + v1.y;
                    lq += v0.x * v0.x + v0.y * v0.y + v1.x * v1.x + v1.y * v1.y;
                    *reinterpret_cast<__half2*>(OutH + iA) = __floats2half2_rn(v0.x, v0.y);
                    *reinterpret_cast<__half2*>(OutH + iB) = __floats2half2_rn(v1.x, v1.y);
                } else if (EPI == 6) {
                    size_t wA = (size_t)mA * HW + n;
                    size_t wB = wA + (size_t)8 * HW;
                    float2 r0 = __half22float2(*reinterpret_cast<const __half2*>(auxh + iA));
                    float2 r1 = __half22float2(*reinterpret_cast<const __half2*>(auxh + iB));
                    float2 w0 = *reinterpret_cast<const float2*>(lnw + wA);
                    float2 w1 = *reinterpret_cast<const float2*>(lnw + wB);
                    float2 l0 = *reinterpret_cast<const float2*>(lnb + wA);
                    float2 l1 = *reinterpret_cast<const float2*>(lnb + wB);
                    v0.x += (r0.x - st.x) * st.y * w0.x + l0.x;
                    v0.y += (r0.y - st.x) * st.y * w0.y + l0.y;
                    v1.x += (r1.x - st.x) * st.y * w1.x + l1.x;
                    v1.y += (r1.y - st.x) * st.y * w1.y + l1.y;
                    *reinterpret_cast<float2*>(Out + iA) = v0;
                    *reinterpret_cast<float2*>(Out + iB) = v1;
                }
            }
        }
        if (EPI == 1) {
            ls = bred_sum(ls);
            lq = bred_sum(lq);
            if (tid == 0)
                part[b * 128 + blockIdx.y * 32 + blockIdx.x] = make_float2(ls, lq);
        }
    }
}

// ===== qsum: per-pixel sum over 512 channels of fp16 expQ (2 px/thread) =====
__global__ __launch_bounds__(256) void colsum(const __half* __restrict__ Qh,
                                              float* __restrict__ qsum) {
    int gid = blockIdx.x * 256 + threadIdx.x;     // 0..32767
    int b = gid >> 11, pp = (gid & 2047) * 2;
    const __half* base = Qh + (size_t)b * PERB + pp;
    float s0 = 0.f, s1 = 0.f;
    #pragma unroll 8
    for (int c = 0; c < CCH; c++) {
        float2 f = __half22float2(*reinterpret_cast<const __half2*>(base + (size_t)c * HW));
        s0 += f.x; s1 += f.y;
    }
    qsum[b * HW + pp] = s0;
    qsum[b * HW + pp + 1] = s1;
}

// ================= attention =================
__global__ __launch_bounds__(256) void kv_part(const float* __restrict__ QKV,
                                               float* __restrict__ KVp,
                                               float* __restrict__ ksp) {
    const int cx = blockIdx.x;
    const int bh = blockIdx.y;
    const int b = bh >> 3, h = bh & 7;
    const float* Kb = QKV + (size_t)b * 3 * PERB + PERB     + (size_t)h * HDIM * HW;
    const float* Vb = QKV + (size_t)b * 3 * PERB + 2 * PERB + (size_t)h * HDIM * HW;
    __shared__ float Ks[64][65];
    __shared__ float Vs[64][65];
    const int tid = threadIdx.x;
    const int tx = tid & 15, ty = tid >> 4;
    float acc[4][4] = {};
    float ksloc[4] = {0.f, 0.f, 0.f, 0.f};
    const int pbeg = cx * 512, pend = pbeg + 512;
    for (int p0 = pbeg; p0 < pend; p0 += 64) {
        #pragma unroll
        for (int t = 0; t < 4; t++) {
            int lin = tid + t * 256;
            int r = lin >> 4, c4 = (lin & 15) * 4;
            float4 kv4 = *reinterpret_cast<const float4*>(&Kb[(size_t)r * HW + p0 + c4]);
            float4 vv4 = *reinterpret_cast<const float4*>(&Vb[(size_t)r * HW + p0 + c4]);
            ksloc[t] += kv4.x + kv4.y + kv4.z + kv4.w;
            Ks[r][c4 + 0] = kv4.x; Ks[r][c4 + 1] = kv4.y; Ks[r][c4 + 2] = kv4.z; Ks[r][c4 + 3] = kv4.w;
            Vs[r][c4 + 0] = vv4.x; Vs[r][c4 + 1] = vv4.y; Vs[r][c4 + 2] = vv4.z; Vs[r][c4 + 3] = vv4.w;
        }
        __syncthreads();
        #pragma unroll 8
        for (int p = 0; p < 64; p++) {
            float ra[4], rb[4];
            #pragma unroll
            for (int i = 0; i < 4; i++) ra[i] = Ks[ty * 4 + i][p];
            #pragma unroll
            for (int j = 0; j < 4; j++) rb[j] = Vs[tx * 4 + j][p];
            #pragma unroll
            for (int i = 0; i < 4; i++)
                #pragma unroll
                for (int j = 0; j < 4; j++)
                    acc[i][j] = fmaf(ra[i], rb[j], acc[i][j]);
        }
        __syncthreads();
    }
    #pragma unroll
    for (int t = 0; t < 4; t++) {
        float v = ksloc[t];
        #pragma unroll
        for (int o = 8; o; o >>= 1) v += __shfl_down_sync(0xffffffffu, v, o, 16);
        if ((tid & 15) == 0)
            ksp[((size_t)cx * 128 + bh) * HDIM + (tid >> 4) + 16 * t] = v;
    }
    float* out = KVp + ((size_t)cx * 128 + bh) * (HDIM * HDIM);
    #pragma unroll
    for (int i = 0; i < 4; i++)
        #pragma unroll
        for (int j = 0; j < 4; j++)
            out[(ty * 4 + i) * HDIM + tx * 4 + j] = acc[i][j];
}
__global__ __launch_bounds__(256) void kv_reduce(const float* __restrict__ KVp,
                                                 const float* __restrict__ ksp,
                                                 float* __restrict__ KV) {
    __shared__ float kinv_s[HDIM];
    const int bh = blockIdx.x;
    if (threadIdx.x < HDIM) {
        float s = 0.f;
        #pragma unroll
        for (int cx = 0; cx < 8; cx++)
            s += ksp[((size_t)cx * 128 + bh) * HDIM + threadIdx.x];
        kinv_s[threadIdx.x] = 1.f / s;
    }
    __syncthreads();
    #pragma unroll
    for (int t = 0; t < 16; t++) {
        int e = threadIdx.x + t * 256;
        float s = 0.f;
        #pragma unroll
        for (int cx = 0; cx < 8; cx++)
            s += KVp[((size_t)cx * 128 + bh) * (HDIM * HDIM) + e];
        KV[(size_t)bh * HDIM * HDIM + e] = s * kinv_s[e >> 6];
    }
}
__global__ __launch_bounds__(256) void attn_kernel(const float* __restrict__ KV,
                                                   const __half* __restrict__ Qh,
                                                   const float* __restrict__ qsum,
                                                   __half* __restrict__ Th) {
    const int bh = blockIdx.y;
    const int p0 = blockIdx.x * 64;
    const int b = bh >> 3, h = bh & 7;
    const __half* Qb = Qh + (size_t)b * PERB + (size_t)h * HDIM * HW;
    const float* KVb = KV + (size_t)bh * HDIM * HDIM;
    __shared__ float KVs[64][64];
    __shared__ float Qs[64][68];
    __shared__ unsigned short TT[64][72];
    const int tid = threadIdx.x;
    const int tx = tid & 15, ty = tid >> 4;
    #pragma unroll
    for (int t = 0; t < 2; t++) {
        int lin = tid + t * 256;
        int r = lin >> 3, c8 = (lin & 7) * 8;
        uint4 q4 = *reinterpret_cast<const uint4*>(&Qb[(size_t)r * HW + p0 + c8]);
        const __half2* qh = reinterpret_cast<const __half2*>(&q4);
        #pragma unroll
        for (int j = 0; j < 4; j++) {
            float2 f = __half22float2(qh[j]);
            Qs[r][c8 + j * 2]     = f.x;
            Qs[r][c8 + j * 2 + 1] = f.y;
        }
    }
    #pragma unroll
    for (int t = 0; t < 4; t++) {
        int lin = tid + t * 256;
        int r = lin >> 4, c4 = (lin & 15) * 4;
        *reinterpret_cast<float4*>(&KVs[r][c4]) =
            *reinterpret_cast<const float4*>(&KVb[(size_t)r * HDIM + c4]);
    }
    __syncthreads();
    float acc[4][4] = {};
    #pragma unroll 8
    for (int k = 0; k < 64; k++) {
        float4 q4 = *reinterpret_cast<const float4*>(&Qs[k][tx * 4]);
        float4 a4 = *reinterpret_cast<const float4*>(&KVs[k][ty * 4]);
        float ra[4] = {a4.x, a4.y, a4.z, a4.w};
        float rb[4] = {q4.x, q4.y, q4.z, q4.w};
        #pragma unroll
        for (int i = 0; i < 4; i++)
            #pragma unroll
            for (int j = 0; j < 4; j++)
                acc[i][j] = fmaf(ra[i], rb[j], acc[i][j]);
    }
    const int bq = b * HW + p0 + tx * 4;
    float inv[4];
    #pragma unroll
    for (int j = 0; j < 4; j++) inv[j] = 1.f / qsum[bq + j];
    #pragma unroll
    for (int i = 0; i < 4; i++)
        #pragma unroll
        for (int j = 0; j < 4; j++) {
            __half hv = __float2half_rn(acc[i][j] * inv[j]);
            TT[tx * 4 + j][ty * 4 + i] = *reinterpret_cast<unsigned short*>(&hv);
        }
    __syncthreads();
    #pragma unroll
    for (int t = 0; t < 2; t++) {
        int cc = tid + t * 256;
        int p = cc >> 3, co = (cc & 7) * 8;
        uint4 v = *reinterpret_cast<const uint4*>(&TT[p][co]);
        size_t o = ((size_t)b * HW + p0 + p) * CCH + h * 64 + co;
        *reinterpret_cast<uint4*>(Th + o) = v;
    }
}

// ================= launch =================
extern "C" void kernel_launch(void* const* d_in, const int* in_sizes, int n_in,
                              void* d_out, int out_size) {
    const float* x     = (const float*)d_in[0];
    const float* ln1w  = (const float*)d_in[1];
    const float* ln1b  = (const float*)d_in[2];
    const float* qw    = (const float*)d_in[3];
    const float* qb    = (const float*)d_in[4];
    const float* kw    = (const float*)d_in[5];
    const float* kb    = (const float*)d_in[6];
    const float* vw    = (const float*)d_in[7];
    const float* vb    = (const float*)d_in[8];
    const float* huw   = (const float*)d_in[9];
    const float* hub   = (const float*)d_in[10];
    const float* ln2w  = (const float*)d_in[11];
    const float* ln2b  = (const float*)d_in[12];
    const float* ff1w  = (const float*)d_in[13];
    const float* ff1b  = (const float*)d_in[14];
    const float* ff2w  = (const float*)d_in[15];
    const float* ff2b  = (const float*)d_in[16];
    float* out = (float*)d_out;

    float *QKV, *KVp, *ksp, *KV, *qsum, *bqkv;
    float2 *part, *stats;
    __half *Qh, *Rh, *Th, *Fh, *Wh;
    cudaGetSymbolAddress((void**)&QKV, g_QKV);
    cudaGetSymbolAddress((void**)&Qh, g_Qh);
    cudaGetSymbolAddress((void**)&Rh, g_Rh);
    cudaGetSymbolAddress((void**)&KVp, g_KVp);
    cudaGetSymbolAddress((void**)&ksp, g_ksp);
    cudaGetSymbolAddress((void**)&KV, g_KV);
    cudaGetSymbolAddress((void**)&qsum, g_qsum);
    cudaGetSymbolAddress((void**)&bqkv, g_bqkv);
    cudaGetSymbolAddress((void**)&part, g_part);
    cudaGetSymbolAddress((void**)&stats, g_stats);
    cudaGetSymbolAddress((void**)&Th, g_Th);
    cudaGetSymbolAddress((void**)&Fh, g_Fh);
    cudaGetSymbolAddress((void**)&Wh, g_Wh);

    const int SMEM = 4 * GSTAGE;   // 81920
    cudaFuncSetAttribute(hmma_gemm<1>, cudaFuncAttributeMaxDynamicSharedMemorySize, SMEM);
    cudaFuncSetAttribute(hmma_gemm<2>, cudaFuncAttributeMaxDynamicSharedMemorySize, SMEM);
    cudaFuncSetAttribute(hmma_gemm<5>, cudaFuncAttributeMaxDynamicSharedMemorySize, SMEM);
    cudaFuncSetAttribute(hmma_gemm<6>, cudaFuncAttributeMaxDynamicSharedMemorySize, SMEM);

    const dim3 gT(HW / 32, CCH / 32, BATCH);         // (128, 16, 16)
    const dim3 gQKVg(HW / 128, 1536 / 128, BATCH);   // (32, 12, 16)
    const dim3 gG512(HW / 128, CCH / 128, BATCH);    // (32, 4, 16)
    const dim3 gG2048(HW / 128, DHID / 128, BATCH);  // (32, 16, 16)

    // weights + bias (one launch)
    wconv_all<<<(WTOT + 1536) / 256, 256>>>(qw, kw, vw, huw, ff1w, ff2w, qb, kb, vb, Wh, bqkv);

    // ln1 -> Th
    ln_stats<<<dim3(128, BATCH), 256>>>(x, part);
    ln_finalize<<<BATCH, 128>>>(part, stats);
    conv_t<<<gT, 256>>>(x, ln1w, ln1b, stats, Th);

    // fused QKV GEMM: Q -> fp16 Qh (staged); expK/V -> fp32 QKV
    hmma_gemm<5><<<gQKVg, 256, SMEM>>>(Wh, Th, bqkv, nullptr, nullptr, QKV, Qh, nullptr,
                                       nullptr, nullptr, nullptr, CCH, 1536);

    colsum<<<(BATCH * HW / 2) / 256, 256>>>(Qh, qsum);

    kv_part<<<dim3(8, 128), 256>>>(QKV, KVp, ksp);
    kv_reduce<<<128, 256>>>(KVp, ksp, KV);
    attn_kernel<<<dim3(HW / 64, BATCH * NHEAD), 256>>>(KV, Qh, qsum, Th);

    // Rh = fp16(x + hu(attn)); LN2 partials fused
    hmma_gemm<1><<<gG512, 256, SMEM>>>(Wh + WOFF_HU, Th, hub, x, nullptr, nullptr, Rh, part,
                                       nullptr, nullptr, nullptr, CCH, CCH);
    ln_finalize<<<BATCH, 128>>>(part, stats);

    // ln2(Rh) -> Th
    conv_t_h<<<gT, 256>>>(Rh, ln2w, ln2b, stats, Th);

    // Fh = fp16(gelu(ff1)); out = ln2(Rh) + ff2(Fh)  [fused epilogue]
    hmma_gemm<2><<<gG2048, 256, SMEM>>>(Wh + WOFF_FF1, Th, ff1b, nullptr, nullptr, nullptr, Fh,
                                        nullptr, nullptr, nullptr, nullptr, CCH, DHID);
    hmma_gemm<6><<<gG512, 256, SMEM>>>(Wh + WOFF_FF2, Fh, ff2b, nullptr, Rh, out, nullptr,
                                       nullptr, ln2w, ln2b, stats, DHID, CCH);
}

// round 17
// speedup vs baseline: 1.0616x; 1.0206x over previous
#include <cuda_runtime.h>
#include <cuda_fp16.h>
#include <math.h>
#include <stdint.h>

// ---------------- problem constants ----------------
#define BATCH 16
#define CCH   512
#define HW    4096
#define DHID  2048
#define NHEAD 8
#define HDIM  64
#define PERB  (CCH*HW)
#define NBHW  (BATCH*HW)
#define LN_EPS 1e-5f

// ---------------- device scratch (allocation-free) ----------------
__device__ float g_QKV[(size_t)BATCH*3*PERB];   // rows 512-1023 expK, 1024-1535 V (Q slot unused)
__device__ __half g_Qh[(size_t)BATCH*PERB];     // expQ fp16 channel-major (b,512,HW)
__device__ __half g_Rh[BATCH*PERB];             // residual R = x + hu(attn), fp16
__device__ float g_KVp[8*128*HDIM*HDIM];        // split-K partials
__device__ float g_ksp[8*128*HDIM];             // split-K row-sum partials of expK
__device__ float g_KV [BATCH*NHEAD*HDIM*HDIM];
__device__ float g_qsump[4*NBHW];               // per-128-channel-block partial pixel sums of expQ
__device__ float g_bqkv[3*CCH];
__device__ float2 g_part[BATCH*128];
__device__ float2 g_stats[BATCH];
// fp16 activations pixel-major (b, p, c)
__device__ __half g_Th[(size_t)BATCH*HW*CCH];
__device__ __half g_Fh[(size_t)BATCH*HW*DHID];
// fp16 weights (stacked: q,k,v,hu,ff1,ff2)
#define WOFF_HU  786432
#define WOFF_FF1 1048576
#define WOFF_FF2 2097152
#define WTOT     3145728
__device__ __half g_Wh[WTOT];

// ================= PTX helpers =================
__device__ __forceinline__ uint32_t smem_u32(const void* p) {
    uint32_t a;
    asm("{ .reg .u64 t; cvta.to.shared.u64 t, %1; cvt.u32.u64 %0, t; }" : "=r"(a) : "l"(p));
    return a;
}
__device__ __forceinline__ void cp16(uint32_t dst, const void* src) {
    asm volatile("cp.async.cg.shared.global [%0], [%1], 16;" :: "r"(dst), "l"(src));
}
__device__ __forceinline__ void cp_commit() {
    asm volatile("cp.async.commit_group;" ::: "memory");
}
template <int N>
__device__ __forceinline__ void cp_wait() {
    asm volatile("cp.async.wait_group %0;" :: "n"(N) : "memory");
}
__device__ __forceinline__ void ldm_x4(uint32_t* r, uint32_t addr) {
    asm volatile("ldmatrix.sync.aligned.m8n8.x4.shared.b16 {%0,%1,%2,%3}, [%4];"
                 : "=r"(r[0]), "=r"(r[1]), "=r"(r[2]), "=r"(r[3]) : "r"(addr));
}
__device__ __forceinline__ void mma_f16(float* c, const uint32_t* a, const uint32_t* b) {
    asm("mma.sync.aligned.m16n8k16.row.col.f32.f16.f16.f32 "
        "{%0,%1,%2,%3}, {%4,%5,%6,%7}, {%8,%9}, {%0,%1,%2,%3};"
        : "+f"(c[0]), "+f"(c[1]), "+f"(c[2]), "+f"(c[3])
        : "r"(a[0]), "r"(a[1]), "r"(a[2]), "r"(a[3]), "r"(b[0]), "r"(b[1]));
}

// fast exp on FMA pipe
__device__ __forceinline__ float fexp(float x) {
    float t = x * 1.4426950408889634f;
    float n = rintf(t);
    float r = t - n;
    float p = 0.00015403530393381609f;
    p = fmaf(p, r, 0.0013333558146428443f);
    p = fmaf(p, r, 0.009618129107628477f);
    p = fmaf(p, r, 0.05550410866482158f);
    p = fmaf(p, r, 0.2402265069591007f);
    p = fmaf(p, r, 0.6931471805599453f);
    p = fmaf(p, r, 1.0f);
    int e = __float2int_rn(n);
    return p * __int_as_float((e + 127) << 23);
}

// ================= block reductions =================
__device__ __forceinline__ float bred_sum(float v) {
    __shared__ float sb[8];
    int lane = threadIdx.x & 31, w = threadIdx.x >> 5;
    #pragma unroll
    for (int o = 16; o; o >>= 1) v += __shfl_down_sync(0xffffffffu, v, o);
    if (lane == 0) sb[w] = v;
    __syncthreads();
    if (threadIdx.x < 32) {
        float r = (lane < 8) ? sb[lane] : 0.f;
        #pragma unroll
        for (int o = 4; o; o >>= 1) r += __shfl_down_sync(0xffffffffu, r, o);
        if (lane == 0) sb[0] = r;
    }
    __syncthreads();
    float out = sb[0];
    __syncthreads();
    return out;
}

// ================= weight conversion + bias pack (one launch) =================
__global__ __launch_bounds__(256) void wconv_all(const float* __restrict__ qw,
                                                 const float* __restrict__ kw,
                                                 const float* __restrict__ vw,
                                                 const float* __restrict__ huw,
                                                 const float* __restrict__ ff1w,
                                                 const float* __restrict__ ff2w,
                                                 const float* __restrict__ qb,
                                                 const float* __restrict__ kb,
                                                 const float* __restrict__ vb,
                                                 __half* __restrict__ h,
                                                 float* __restrict__ bq) {
    int i = blockIdx.x * 256 + threadIdx.x;
    if (i < WTOT) {
        float v;
        if (i < 786432) {
            int seg = i >> 18, off = i & 262143;
            v = (seg == 0) ? qw[off] : (seg == 1) ? kw[off] : vw[off];
        } else if (i < 1048576) {
            v = huw[i - 786432];
        } else if (i < 2097152) {
            v = ff1w[i - 1048576];
        } else {
            v = ff2w[i - 2097152];
        }
        h[i] = __float2half_rn(v);
    } else {
        int j = i - WTOT;
        if (j < 512) bq[j] = qb[j];
        else if (j < 1024) bq[j] = kb[j - 512];
        else if (j < 1536) bq[j] = vb[j - 1024];
    }
}

// ================= LayerNorm stats =================
__global__ __launch_bounds__(256) void ln_stats(const float* __restrict__ in,
                                                float2* __restrict__ part) {
    int b = blockIdx.y, pb = blockIdx.x;
    const float* p = in + (size_t)b * PERB + (size_t)pb * 16384;
    float s = 0.f, q = 0.f;
    #pragma unroll
    for (int i = 0; i < 16; i++) {
        float4 v = *reinterpret_cast<const float4*>(p + (size_t)(threadIdx.x + i * 256) * 4);
        s += v.x + v.y + v.z + v.w;
        q += v.x * v.x + v.y * v.y + v.z * v.z + v.w * v.w;
    }
    s = bred_sum(s);
    q = bred_sum(q);
    if (threadIdx.x == 0) part[b * 128 + pb] = make_float2(s, q);
}
__global__ __launch_bounds__(128) void ln_finalize(const float2* __restrict__ part,
                                                   float2* __restrict__ stats) {
    __shared__ double ss[128], qq[128];
    const int b = blockIdx.x, t = threadIdx.x;
    float2 p = part[b * 128 + t];
    ss[t] = (double)p.x;
    qq[t] = (double)p.y;
    __syncthreads();
    #pragma unroll
    for (int o = 64; o; o >>= 1) {
        if (t < o) { ss[t] += ss[t + o]; qq[t] += qq[t + o]; }
        __syncthreads();
    }
    if (t == 0) {
        double invN = 1.0 / (double)PERB;
        double mu = ss[0] * invN;
        double var = qq[0] * invN - mu * mu;
        double rstd = 1.0 / sqrt(var + (double)LN_EPS);
        stats[b] = make_float2((float)mu, (float)rstd);
    }
}

// ===== conv_t: fp32 (b,512,HW) -> LN -> fp16 (b,HW,512) =====
__global__ __launch_bounds__(256) void conv_t(const float* __restrict__ in,
                                              const float* __restrict__ lnw,
                                              const float* __restrict__ lnb,
                                              const float2* __restrict__ stats,
                                              __half* __restrict__ oh) {
    __shared__ float T[32][33];
    const int p0 = blockIdx.x * 32, c0 = blockIdx.y * 32, b = blockIdx.z;
    const int t = threadIdx.x;
    {
        int cl = t >> 3, p4 = (t & 7) * 4;
        size_t gidx = ((size_t)b * CCH + c0 + cl) * HW + p0 + p4;
        float4 v = *reinterpret_cast<const float4*>(in + gidx);
        float2 st = stats[b];
        size_t widx = (size_t)(c0 + cl) * HW + p0 + p4;
        float4 wv = *reinterpret_cast<const float4*>(lnw + widx);
        float4 bv = *reinterpret_cast<const float4*>(lnb + widx);
        v.x = (v.x - st.x) * st.y * wv.x + bv.x;
        v.y = (v.y - st.x) * st.y * wv.y + bv.y;
        v.z = (v.z - st.x) * st.y * wv.z + bv.z;
        v.w = (v.w - st.x) * st.y * wv.w + bv.w;
        T[cl][p4 + 0] = v.x; T[cl][p4 + 1] = v.y; T[cl][p4 + 2] = v.z; T[cl][p4 + 3] = v.w;
    }
    __syncthreads();
    {
        int pl = t >> 3, c4 = (t & 7) * 4;
        unsigned short hb[4];
        #pragma unroll
        for (int j = 0; j < 4; j++) {
            __half hv = __float2half_rn(T[c4 + j][pl]);
            hb[j] = *reinterpret_cast<unsigned short*>(&hv);
        }
        uint2 pk;
        pk.x = (unsigned int)hb[0] | ((unsigned int)hb[1] << 16);
        pk.y = (unsigned int)hb[2] | ((unsigned int)hb[3] << 16);
        size_t o = ((size_t)b * HW + p0 + pl) * CCH + c0 + c4;
        *reinterpret_cast<uint2*>(oh + o) = pk;
    }
}

// ===== conv_t_h: fp16 R (b,512,HW) -> LN -> fp16 (b,HW,512) =====
__global__ __launch_bounds__(256) void conv_t_h(const __half* __restrict__ in,
                                                const float* __restrict__ lnw,
                                                const float* __restrict__ lnb,
                                                const float2* __restrict__ stats,
                                                __half* __restrict__ oh) {
    __shared__ float T[32][33];
    const int p0 = blockIdx.x * 32, c0 = blockIdx.y * 32, b = blockIdx.z;
    const int t = threadIdx.x;
    {
        int cl = t >> 3, p4 = (t & 7) * 4;
        size_t gidx = ((size_t)b * CCH + c0 + cl) * HW + p0 + p4;
        uint2 hv2 = *reinterpret_cast<const uint2*>(in + gidx);
        const __half2* hp = reinterpret_cast<const __half2*>(&hv2);
        float2 f0 = __half22float2(hp[0]);
        float2 f1 = __half22float2(hp[1]);
        float4 v = make_float4(f0.x, f0.y, f1.x, f1.y);
        float2 st = stats[b];
        size_t widx = (size_t)(c0 + cl) * HW + p0 + p4;
        float4 wv = *reinterpret_cast<const float4*>(lnw + widx);
        float4 bv = *reinterpret_cast<const float4*>(lnb + widx);
        v.x = (v.x - st.x) * st.y * wv.x + bv.x;
        v.y = (v.y - st.x) * st.y * wv.y + bv.y;
        v.z = (v.z - st.x) * st.y * wv.z + bv.z;
        v.w = (v.w - st.x) * st.y * wv.w + bv.w;
        T[cl][p4 + 0] = v.x; T[cl][p4 + 1] = v.y; T[cl][p4 + 2] = v.z; T[cl][p4 + 3] = v.w;
    }
    __syncthreads();
    {
        int pl = t >> 3, c4 = (t & 7) * 4;
        unsigned short hb[4];
        #pragma unroll
        for (int j = 0; j < 4; j++) {
            __half hv = __float2half_rn(T[c4 + j][pl]);
            hb[j] = *reinterpret_cast<unsigned short*>(&hv);
        }
        uint2 pk;
        pk.x = (unsigned int)hb[0] | ((unsigned int)hb[1] << 16);
        pk.y = (unsigned int)hb[2] | ((unsigned int)hb[3] << 16);
        size_t o = ((size_t)b * HW + p0 + pl) * CCH + c0 + c4;
        *reinterpret_cast<uint2*>(oh + o) = pk;
    }
}

// ================= HMMA fp16 GEMM (mma.sync, cp.async 4-stage, 2 CTA/SM) =================
// EPI 1: +bias+aux -> fp16 R (OutH) + LN partial sums
// EPI 2: gelu(+bias) -> fp16 pixel-major
// EPI 5: QKV: m0<512 -> exp -> fp16 Qh (staged) + per-pixel partial sums; m0<1024 -> exp fp32; else +bias
// EPI 6: ln2(auxh)+bias+acc -> fp32
#define GSTAGE 20480
template <int EPI>
__global__ __launch_bounds__(256, 2)
void hmma_gemm(const __half* __restrict__ wh,
               const __half* __restrict__ ah,
               const float* __restrict__ bias, const float* __restrict__ aux,
               const __half* __restrict__ auxh,
               float* __restrict__ Out, __half* __restrict__ OutH,
               float2* __restrict__ part, float* __restrict__ qsump,
               const float* __restrict__ lnw, const float* __restrict__ lnb,
               const float2* __restrict__ stats, int K, int M) {
    extern __shared__ unsigned char smem_raw[];
    const uint32_t sb0 = smem_u32(smem_raw);

    const int tid = threadIdx.x;
    const int lane = tid & 31, wid = tid >> 5;
    const int wm = wid & 3, wn = wid >> 2;
    const int n0 = blockIdx.x * 128, m0 = blockIdx.y * 128, b = blockIdx.z;

    const __half* A0 = wh + (size_t)m0 * K;
    const __half* B0 = ah + ((size_t)b * HW + n0) * K;

    const int r0 = tid >> 2, c0c = tid & 3;
    const int r1 = (tid + 256) >> 2;
    const uint32_t s0 = (uint32_t)(r0 * 80 + c0c * 16);
    const uint32_t s1 = (uint32_t)(r1 * 80 + c0c * 16);
    const size_t g0 = (size_t)r0 * K + c0c * 8;
    const size_t g1 = (size_t)r1 * K + c0c * 8;

    const uint32_t aoff = (uint32_t)((wm * 32 + (lane & 15)) * 80 + (lane >> 4) * 16);
    const uint32_t boff = (uint32_t)(10240 +
        (wn * 64 + (lane & 7) + ((lane >> 4) << 3)) * 80 + ((lane >> 3) & 1) * 16);

    float acc[2][8][4];
    #pragma unroll
    for (int i = 0; i < 2; i++)
        #pragma unroll
        for (int j = 0; j < 8; j++)
            #pragma unroll
            for (int q = 0; q < 4; q++) acc[i][j][q] = 0.f;

    const int NIT = K >> 5;

    #pragma unroll
    for (int s = 0; s < 3; s++) {
        uint32_t sbs = sb0 + s * GSTAGE;
        size_t k0 = (size_t)s * 32;
        cp16(sbs + s0,         A0 + g0 + k0);  cp16(sbs + s1,         A0 + g1 + k0);
        cp16(sbs + 10240 + s0, B0 + g0 + k0);  cp16(sbs + 10240 + s1, B0 + g1 + k0);
        cp_commit();
    }

    for (int it = 0; it < NIT; it++) {
        cp_wait<2>();
        __syncthreads();

        if (it + 3 < NIT) {
            int ls = (it + 3) & 3;
            uint32_t sbs = sb0 + ls * GSTAGE;
            size_t k0 = (size_t)(it + 3) * 32;
            cp16(sbs + s0,         A0 + g0 + k0);  cp16(sbs + s1,         A0 + g1 + k0);
            cp16(sbs + 10240 + s0, B0 + g0 + k0);  cp16(sbs + 10240 + s1, B0 + g1 + k0);
        }
        cp_commit();

        const uint32_t sbs = sb0 + (it & 3) * GSTAGE;
        #pragma unroll
        for (int kk = 0; kk < 2; kk++) {
            const uint32_t kb = kk * 32;
            uint32_t ra[2][4], rb[4][4];
            #pragma unroll
            for (int mi = 0; mi < 2; mi++)
                ldm_x4(ra[mi], sbs + aoff + mi * 1280 + kb);
            #pragma unroll
            for (int ni = 0; ni < 4; ni++)
                ldm_x4(rb[ni], sbs + boff + ni * 1280 + kb);
            #pragma unroll
            for (int mi = 0; mi < 2; mi++)
                #pragma unroll
                for (int ni = 0; ni < 4; ni++)
                    #pragma unroll
                    for (int j = 0; j < 2; j++)
                        mma_f16(acc[mi][ni * 2 + j], ra[mi], &rb[ni][j * 2]);
        }
    }

    if (EPI == 2) {
        cp_wait<0>();
        __syncthreads();
        unsigned short* T = reinterpret_cast<unsigned short*>(smem_raw);   // [128][144]
        const int lm0 = wm * 32 + (lane >> 2);
        const int ln0 = wn * 64 + (lane & 3) * 2;
        #pragma unroll
        for (int mi = 0; mi < 2; mi++) {
            const int mA = lm0 + mi * 16;
            const float bv0 = __ldg(bias + m0 + mA);
            const float bv1 = __ldg(bias + m0 + mA + 8);
            #pragma unroll
            for (int nf = 0; nf < 8; nf++) {
                const int n = ln0 + nf * 8;
                float v0 = acc[mi][nf][0] + bv0;
                float v1 = acc[mi][nf][1] + bv0;
                float v2 = acc[mi][nf][2] + bv1;
                float v3 = acc[mi][nf][3] + bv1;
                v0 = 0.5f * v0 * (1.0f + erff(v0 * 0.70710678118654752f));
                v1 = 0.5f * v1 * (1.0f + erff(v1 * 0.70710678118654752f));
                v2 = 0.5f * v2 * (1.0f + erff(v2 * 0.70710678118654752f));
                v3 = 0.5f * v3 * (1.0f + erff(v3 * 0.70710678118654752f));
                __half h0 = __float2half_rn(v0), h1 = __float2half_rn(v1);
                __half h2 = __float2half_rn(v2), h3 = __float2half_rn(v3);
                T[n * 144 + mA]           = *reinterpret_cast<unsigned short*>(&h0);
                T[(n + 1) * 144 + mA]     = *reinterpret_cast<unsigned short*>(&h1);
                T[n * 144 + mA + 8]       = *reinterpret_cast<unsigned short*>(&h2);
                T[(n + 1) * 144 + mA + 8] = *reinterpret_cast<unsigned short*>(&h3);
            }
        }
        __syncthreads();
        #pragma unroll
        for (int i = 0; i < 8; i++) {
            int cc = tid + i * 256;
            int row = cc >> 4, cq = cc & 15;
            uint4 v = *reinterpret_cast<const uint4*>(T + row * 144 + cq * 8);
            size_t o = ((size_t)b * HW + n0 + row) * (size_t)M + m0 + cq * 8;
            *reinterpret_cast<uint4*>(OutH + o) = v;
        }
    } else if (EPI == 5 && m0 < 512) {
        // Q rows: exp(+bias) -> fp16 via smem staging; plus per-pixel partial channel sums
        cp_wait<0>();
        __syncthreads();
        unsigned short* T = reinterpret_cast<unsigned short*>(smem_raw);   // [128][136]
        const int lm0 = wm * 32 + (lane >> 2);
        const int ln0 = wn * 64 + (lane & 3) * 2;
        #pragma unroll
        for (int mi = 0; mi < 2; mi++) {
            const int mA = lm0 + mi * 16;
            const float bv0 = __ldg(bias + m0 + mA);
            const float bv1 = __ldg(bias + m0 + mA + 8);
            #pragma unroll
            for (int nf = 0; nf < 8; nf++) {
                const int n = ln0 + nf * 8;
                float v0 = fexp(acc[mi][nf][0] + bv0);
                float v1 = fexp(acc[mi][nf][1] + bv0);
                float v2 = fexp(acc[mi][nf][2] + bv1);
                float v3 = fexp(acc[mi][nf][3] + bv1);
                *reinterpret_cast<__half2*>(T + mA * 136 + n)       = __floats2half2_rn(v0, v1);
                *reinterpret_cast<__half2*>(T + (mA + 8) * 136 + n) = __floats2half2_rn(v2, v3);
            }
        }
        __syncthreads();
        #pragma unroll
        for (int i = 0; i < 8; i++) {
            int cc = tid + i * 256;
            int row = cc >> 4, cq = cc & 15;
            uint4 v = *reinterpret_cast<const uint4*>(T + row * 136 + cq * 8);
            size_t o = ((size_t)b * CCH + m0 + row) * HW + n0 + cq * 8;
            *reinterpret_cast<uint4*>(OutH + o) = v;
        }
        // per-pixel partial sum over this block's 128 channels (threads 0..127)
        if (tid < 128) {
            float s = 0.f;
            #pragma unroll 8
            for (int r = 0; r < 128; r++) {
                __half hv = *reinterpret_cast<const __half*>(T + r * 136 + tid);
                s += __half2float(hv);
            }
            qsump[(size_t)(m0 >> 7) * NBHW + (size_t)b * HW + n0 + tid] = s;
        }
    } else {
        const bool doexp = (EPI == 5) && (m0 < 1024);
        const int mrow = m0 + wm * 32 + (lane >> 2);
        const int ncol = n0 + wn * 64 + (lane & 3) * 2;
        float ls = 0.f, lq = 0.f;
        float2 st;
        if (EPI == 6) st = stats[b];
        #pragma unroll
        for (int mi = 0; mi < 2; mi++) {
            const int mA = mrow + mi * 16;
            const float bv0 = __ldg(bias + mA);
            const float bv1 = __ldg(bias + mA + 8);
            #pragma unroll
            for (int nf = 0; nf < 8; nf++) {
                const int n = ncol + nf * 8;
                size_t iA = ((size_t)b * M + mA) * HW + n;
                size_t iB = iA + (size_t)8 * HW;
                float2 v0 = make_float2(acc[mi][nf][0] + bv0, acc[mi][nf][1] + bv0);
                float2 v1 = make_float2(acc[mi][nf][2] + bv1, acc[mi][nf][3] + bv1);
                if (EPI == 5) {
                    if (doexp) {
                        v0.x = fexp(v0.x); v0.y = fexp(v0.y);
                        v1.x = fexp(v1.x); v1.y = fexp(v1.y);
                    }
                    *reinterpret_cast<float2*>(Out + iA) = v0;
                    *reinterpret_cast<float2*>(Out + iB) = v1;
                } else if (EPI == 1) {
                    float2 a0 = *reinterpret_cast<const float2*>(aux + iA);
                    float2 a1 = *reinterpret_cast<const float2*>(aux + iB);
                    v0.x += a0.x; v0.y += a0.y; v1.x += a1.x; v1.y += a1.y;
                    ls += v0.x + v0.y + v1.x + v1.y;
                    lq += v0.x * v0.x + v0.y * v0.y + v1.x * v1.x + v1.y * v1.y;
                    *reinterpret_cast<__half2*>(OutH + iA) = __floats2half2_rn(v0.x, v0.y);
                    *reinterpret_cast<__half2*>(OutH + iB) = __floats2half2_rn(v1.x, v1.y);
                } else if (EPI == 6) {
                    size_t wA = (size_t)mA * HW + n;
                    size_t wB = wA + (size_t)8 * HW;
                    float2 r0 = __half22float2(*reinterpret_cast<const __half2*>(auxh + iA));
                    float2 r1 = __half22float2(*reinterpret_cast<const __half2*>(auxh + iB));
                    float2 w0 = *reinterpret_cast<const float2*>(lnw + wA);
                    float2 w1 = *reinterpret_cast<const float2*>(lnw + wB);
                    float2 l0 = *reinterpret_cast<const float2*>(lnb + wA);
                    float2 l1 = *reinterpret_cast<const float2*>(lnb + wB);
                    v0.x += (r0.x - st.x) * st.y * w0.x + l0.x;
                    v0.y += (r0.y - st.x) * st.y * w0.y + l0.y;
                    v1.x += (r1.x - st.x) * st.y * w1.x + l1.x;
                    v1.y += (r1.y - st.x) * st.y * w1.y + l1.y;
                    *reinterpret_cast<float2*>(Out + iA) = v0;
                    *reinterpret_cast<float2*>(Out + iB) = v1;
                }
            }
        }
        if (EPI == 1) {
            ls = bred_sum(ls);
            lq = bred_sum(lq);
            if (tid == 0)
                part[b * 128 + blockIdx.y * 32 + blockIdx.x] = make_float2(ls, lq);
        }
    }
}

// ================= attention =================
__global__ __launch_bounds__(256) void kv_part(const float* __restrict__ QKV,
                                               float* __restrict__ KVp,
                                               float* __restrict__ ksp) {
    const int cx = blockIdx.x;
    const int bh = blockIdx.y;
    const int b = bh >> 3, h = bh & 7;
    const float* Kb = QKV + (size_t)b * 3 * PERB + PERB     + (size_t)h * HDIM * HW;
    const float* Vb = QKV + (size_t)b * 3 * PERB + 2 * PERB + (size_t)h * HDIM * HW;
    __shared__ float Ks[64][65];
    __shared__ float Vs[64][65];
    const int tid = threadIdx.x;
    const int tx = tid & 15, ty = tid >> 4;
    float acc[4][4] = {};
    float ksloc[4] = {0.f, 0.f, 0.f, 0.f};
    const int pbeg = cx * 512, pend = pbeg + 512;
    for (int p0 = pbeg; p0 < pend; p0 += 64) {
        #pragma unroll
        for (int t = 0; t < 4; t++) {
            int lin = tid + t * 256;
            int r = lin >> 4, c4 = (lin & 15) * 4;
            float4 kv4 = *reinterpret_cast<const float4*>(&Kb[(size_t)r * HW + p0 + c4]);
            float4 vv4 = *reinterpret_cast<const float4*>(&Vb[(size_t)r * HW + p0 + c4]);
            ksloc[t] += kv4.x + kv4.y + kv4.z + kv4.w;
            Ks[r][c4 + 0] = kv4.x; Ks[r][c4 + 1] = kv4.y; Ks[r][c4 + 2] = kv4.z; Ks[r][c4 + 3] = kv4.w;
            Vs[r][c4 + 0] = vv4.x; Vs[r][c4 + 1] = vv4.y; Vs[r][c4 + 2] = vv4.z; Vs[r][c4 + 3] = vv4.w;
        }
        __syncthreads();
        #pragma unroll 8
        for (int p = 0; p < 64; p++) {
            float ra[4], rb[4];
            #pragma unroll
            for (int i = 0; i < 4; i++) ra[i] = Ks[ty * 4 + i][p];
            #pragma unroll
            for (int j = 0; j < 4; j++) rb[j] = Vs[tx * 4 + j][p];
            #pragma unroll
            for (int i = 0; i < 4; i++)
                #pragma unroll
                for (int j = 0; j < 4; j++)
                    acc[i][j] = fmaf(ra[i], rb[j], acc[i][j]);
        }
        __syncthreads();
    }
    #pragma unroll
    for (int t = 0; t < 4; t++) {
        float v = ksloc[t];
        #pragma unroll
        for (int o = 8; o; o >>= 1) v += __shfl_down_sync(0xffffffffu, v, o, 16);
        if ((tid & 15) == 0)
            ksp[((size_t)cx * 128 + bh) * HDIM + (tid >> 4) + 16 * t] = v;
    }
    float* out = KVp + ((size_t)cx * 128 + bh) * (HDIM * HDIM);
    #pragma unroll
    for (int i = 0; i < 4; i++)
        #pragma unroll
        for (int j = 0; j < 4; j++)
            out[(ty * 4 + i) * HDIM + tx * 4 + j] = acc[i][j];
}
__global__ __launch_bounds__(256) void kv_reduce(const float* __restrict__ KVp,
                                                 const float* __restrict__ ksp,
                                                 float* __restrict__ KV) {
    __shared__ float kinv_s[HDIM];
    const int bh = blockIdx.x;
    if (threadIdx.x < HDIM) {
        float s = 0.f;
        #pragma unroll
        for (int cx = 0; cx < 8; cx++)
            s += ksp[((size_t)cx * 128 + bh) * HDIM + threadIdx.x];
        kinv_s[threadIdx.x] = 1.f / s;
    }
    __syncthreads();
    #pragma unroll
    for (int t = 0; t < 16; t++) {
        int e = threadIdx.x + t * 256;
        float s = 0.f;
        #pragma unroll
        for (int cx = 0; cx < 8; cx++)
            s += KVp[((size_t)cx * 128 + bh) * (HDIM * HDIM) + e];
        KV[(size_t)bh * HDIM * HDIM + e] = s * kinv_s[e >> 6];
    }
}
__global__ __launch_bounds__(256) void attn_kernel(const float* __restrict__ KV,
                                                   const __half* __restrict__ Qh,
                                                   const float* __restrict__ qsump,
                                                   __half* __restrict__ Th) {
    const int bh = blockIdx.y;
    const int p0 = blockIdx.x * 64;
    const int b = bh >> 3, h = bh & 7;
    const __half* Qb = Qh + (size_t)b * PERB + (size_t)h * HDIM * HW;
    const float* KVb = KV + (size_t)bh * HDIM * HDIM;
    __shared__ float KVs[64][64];
    __shared__ float Qs[64][68];
    __shared__ unsigned short TT[64][72];
    const int tid = threadIdx.x;
    const int tx = tid & 15, ty = tid >> 4;
    #pragma unroll
    for (int t = 0; t < 2; t++) {
        int lin = tid + t * 256;
        int r = lin >> 3, c8 = (lin & 7) * 8;
        uint4 q4 = *reinterpret_cast<const uint4*>(&Qb[(size_t)r * HW + p0 + c8]);
        const __half2* qh = reinterpret_cast<const __half2*>(&q4);
        #pragma unroll
        for (int j = 0; j < 4; j++) {
            float2 f = __half22float2(qh[j]);
            Qs[r][c8 + j * 2]     = f.x;
            Qs[r][c8 + j * 2 + 1] = f.y;
        }
    }
    #pragma unroll
    for (int t = 0; t < 4; t++) {
        int lin = tid + t * 256;
        int r = lin >> 4, c4 = (lin & 15) * 4;
        *reinterpret_cast<float4*>(&KVs[r][c4]) =
            *reinterpret_cast<const float4*>(&KVb[(size_t)r * HDIM + c4]);
    }
    __syncthreads();
    float acc[4][4] = {};
    #pragma unroll 8
    for (int k = 0; k < 64; k++) {
        float4 q4 = *reinterpret_cast<const float4*>(&Qs[k][tx * 4]);
        float4 a4 = *reinterpret_cast<const float4*>(&KVs[k][ty * 4]);
        float ra[4] = {a4.x, a4.y, a4.z, a4.w};
        float rb[4] = {q4.x, q4.y, q4.z, q4.w};
        #pragma unroll
        for (int i = 0; i < 4; i++)
            #pragma unroll
            for (int j = 0; j < 4; j++)
                acc[i][j] = fmaf(ra[i], rb[j], acc[i][j]);
    }
    const size_t bq = (size_t)b * HW + p0 + tx * 4;
    float inv[4];
    #pragma unroll
    for (int j = 0; j < 4; j++) {
        float s = qsump[bq + j] + qsump[NBHW + bq + j]
                + qsump[2 * (size_t)NBHW + bq + j] + qsump[3 * (size_t)NBHW + bq + j];
        inv[j] = 1.f / s;
    }
    #pragma unroll
    for (int i = 0; i < 4; i++)
        #pragma unroll
        for (int j = 0; j < 4; j++) {
            __half hv = __float2half_rn(acc[i][j] * inv[j]);
            TT[tx * 4 + j][ty * 4 + i] = *reinterpret_cast<unsigned short*>(&hv);
        }
    __syncthreads();
    #pragma unroll
    for (int t = 0; t < 2; t++) {
        int cc = tid + t * 256;
        int p = cc >> 3, co = (cc & 7) * 8;
        uint4 v = *reinterpret_cast<const uint4*>(&TT[p][co]);
        size_t o = ((size_t)b * HW + p0 + p) * CCH + h * 64 + co;
        *reinterpret_cast<uint4*>(Th + o) = v;
    }
}

// ================= launch =================
extern "C" void kernel_launch(void* const* d_in, const int* in_sizes, int n_in,
                              void* d_out, int out_size) {
    const float* x     = (const float*)d_in[0];
    const float* ln1w  = (const float*)d_in[1];
    const float* ln1b  = (const float*)d_in[2];
    const float* qw    = (const float*)d_in[3];
    const float* qb    = (const float*)d_in[4];
    const float* kw    = (const float*)d_in[5];
    const float* kb    = (const float*)d_in[6];
    const float* vw    = (const float*)d_in[7];
    const float* vb    = (const float*)d_in[8];
    const float* huw   = (const float*)d_in[9];
    const float* hub   = (const float*)d_in[10];
    const float* ln2w  = (const float*)d_in[11];
    const float* ln2b  = (const float*)d_in[12];
    const float* ff1w  = (const float*)d_in[13];
    const float* ff1b  = (const float*)d_in[14];
    const float* ff2w  = (const float*)d_in[15];
    const float* ff2b  = (const float*)d_in[16];
    float* out = (float*)d_out;

    float *QKV, *KVp, *ksp, *KV, *qsump, *bqkv;
    float2 *part, *stats;
    __half *Qh, *Rh, *Th, *Fh, *Wh;
    cudaGetSymbolAddress((void**)&QKV, g_QKV);
    cudaGetSymbolAddress((void**)&Qh, g_Qh);
    cudaGetSymbolAddress((void**)&Rh, g_Rh);
    cudaGetSymbolAddress((void**)&KVp, g_KVp);
    cudaGetSymbolAddress((void**)&ksp, g_ksp);
    cudaGetSymbolAddress((void**)&KV, g_KV);
    cudaGetSymbolAddress((void**)&qsump, g_qsump);
    cudaGetSymbolAddress((void**)&bqkv, g_bqkv);
    cudaGetSymbolAddress((void**)&part, g_part);
    cudaGetSymbolAddress((void**)&stats, g_stats);
    cudaGetSymbolAddress((void**)&Th, g_Th);
    cudaGetSymbolAddress((void**)&Fh, g_Fh);
    cudaGetSymbolAddress((void**)&Wh, g_Wh);

    const int SMEM = 4 * GSTAGE;   // 81920
    cudaFuncSetAttribute(hmma_gemm<1>, cudaFuncAttributeMaxDynamicSharedMemorySize, SMEM);
    cudaFuncSetAttribute(hmma_gemm<2>, cudaFuncAttributeMaxDynamicSharedMemorySize, SMEM);
    cudaFuncSetAttribute(hmma_gemm<5>, cudaFuncAttributeMaxDynamicSharedMemorySize, SMEM);
    cudaFuncSetAttribute(hmma_gemm<6>, cudaFuncAttributeMaxDynamicSharedMemorySize, SMEM);

    const dim3 gT(HW / 32, CCH / 32, BATCH);         // (128, 16, 16)
    const dim3 gQKVg(HW / 128, 1536 / 128, BATCH);   // (32, 12, 16)
    const dim3 gG512(HW / 128, CCH / 128, BATCH);    // (32, 4, 16)
    const dim3 gG2048(HW / 128, DHID / 128, BATCH);  // (32, 16, 16)

    // weights + bias (one launch)
    wconv_all<<<(WTOT + 1536) / 256, 256>>>(qw, kw, vw, huw, ff1w, ff2w, qb, kb, vb, Wh, bqkv);

    // ln1 -> Th
    ln_stats<<<dim3(128, BATCH), 256>>>(x, part);
    ln_finalize<<<BATCH, 128>>>(part, stats);
    conv_t<<<gT, 256>>>(x, ln1w, ln1b, stats, Th);

    // fused QKV GEMM: Q -> fp16 Qh + qsum partials; expK/V -> fp32 QKV
    hmma_gemm<5><<<gQKVg, 256, SMEM>>>(Wh, Th, bqkv, nullptr, nullptr, QKV, Qh, nullptr, qsump,
                                       nullptr, nullptr, nullptr, CCH, 1536);

    kv_part<<<dim3(8, 128), 256>>>(QKV, KVp, ksp);
    kv_reduce<<<128, 256>>>(KVp, ksp, KV);
    attn_kernel<<<dim3(HW / 64, BATCH * NHEAD), 256>>>(KV, Qh, qsump, Th);

    // Rh = fp16(x + hu(attn)); LN2 partials fused
    hmma_gemm<1><<<gG512, 256, SMEM>>>(Wh + WOFF_HU, Th, hub, x, nullptr, nullptr, Rh, part, nullptr,
                                       nullptr, nullptr, nullptr, CCH, CCH);
    ln_finalize<<<BATCH, 128>>>(part, stats);

    // ln2(Rh) -> Th
    conv_t_h<<<gT, 256>>>(Rh, ln2w, ln2b, stats, Th);

    // Fh = fp16(gelu(ff1)); out = ln2(Rh) + ff2(Fh)  [fused epilogue]
    hmma_gemm<2><<<gG2048, 256, SMEM>>>(Wh + WOFF_FF1, Th, ff1b, nullptr, nullptr, nullptr, Fh,
                                        nullptr, nullptr, nullptr, nullptr, nullptr, CCH, DHID);
    hmma_gemm<6><<<gG512, 256, SMEM>>>(Wh + WOFF_FF2, Fh, ff2b, nullptr, Rh, out, nullptr, nullptr,
                                       nullptr, ln2w, ln2b, stats, DHID, CCH);
}